// round 9
// baseline (speedup 1.0000x reference)
#include <cuda_runtime.h>
#include <cuda_bf16.h>
#include <math.h>
#include <stdint.h>

#define Nn 40000
#define Ee 320000
#define Dd 128
#define Hh 4
#define DK 32
#define Tt 3
#define Rr 5
#define Kk 3
#define ND 5120000      // N*D
#define EH 1280000      // E*H
#define NH 160000       // N*H
#define RELF 20480      // R*H*DK*DK floats

typedef unsigned long long ull;

// ---------------- device scratch ----------------
__device__ __align__(16) float g_qn[ND];
__device__ __align__(16) float g_kn[ND];
__device__ __align__(16) float g_vn[ND];
__device__ __align__(16) float g_knr[Rr * ND];   // [r][n][128]
__device__ __align__(16) float g_ex[EH];
__device__ __align__(16) float g_mx[NH];
__device__ __align__(16) float g_den[NH];
__device__ int   g_deg[Nn];
__device__ int   g_perm[Nn];
__device__ int   g_tcount[Tt];
__device__ int   g_toff[Tt + 1];
__device__ int   g_cursor[Tt];
__device__ __align__(16) float g_agg[Kk * ND];
__device__ __align__(16) float g_aggm[Kk * ND];
__device__ __align__(16) float g_front[Kk * ND];
__device__ __align__(16) float g_tail[Kk * ND];
__device__ __align__(16) float g_hbuf[ND];
__device__ __align__(16) float g_trans[ND];
__device__ __align__(16) float g_wcomb[Kk * 16384];
__device__ __align__(16) float g_bfront[Kk * 128];

// pre-split bf16 planes
// weight plane order: 0-2 q, 3-5 k, 6-8 v, 9-11 a_w, 12-14 WMk, 15-17 wcomb,
//                     18 Wkl, 19-23 rel_att(dense block-diag)
#define NWMAT 24
__device__ __align__(16) uint32_t g_bsh[NWMAT * 8192];
__device__ __align__(16) uint32_t g_bsl[NWMAT * 8192];
__device__ __align__(16) uint32_t g_metah[Nn * 64];
__device__ __align__(16) uint32_t g_metal[Nn * 64];
__device__ __align__(16) uint32_t g_knh[Nn * 64];
__device__ __align__(16) uint32_t g_knl[Nn * 64];

// ---------------- small helpers ----------------
__device__ __forceinline__ float sigmoidf_(float x) { return 1.0f / (1.0f + expf(-x)); }

__device__ __forceinline__ void atomicMaxF(float* addr, float v) {
    int old = __float_as_int(*addr);
    while (__int_as_float(old) < v) {
        int prev = atomicCAS((int*)addr, old, __float_as_int(v));
        if (prev == old) break;
        old = prev;
    }
}

__device__ __forceinline__ void fma2(ull& d, ull a, ull b) {
    asm("fma.rn.f32x2 %0, %1, %2, %0;" : "+l"(d) : "l"(a), "l"(b));
}
__device__ __forceinline__ ull dup2(float x) {
    ull r; asm("mov.b64 %0, {%1, %1};" : "=l"(r) : "f"(x)); return r;
}
__device__ __forceinline__ ull pack2(float x, float y) {
    ull r; asm("mov.b64 %0, {%1, %2};" : "=l"(r) : "f"(x), "f"(y)); return r;
}
__device__ __forceinline__ float2 unpack2(ull v) {
    float2 f; asm("mov.b64 {%0, %1}, %2;" : "=f"(f.x), "=f"(f.y) : "l"(v)); return f;
}

// pack two floats to bf16x2 (low = x, high = y), round-to-nearest
__device__ __forceinline__ uint32_t pack_bf16(float x, float y) {
    uint32_t r; asm("cvt.rn.bf16x2.f32 %0, %1, %2;" : "=r"(r) : "f"(y), "f"(x));
    return r;
}
// split pair (x,y) into hi bf16x2 + lo bf16x2 (residual)
__device__ __forceinline__ void split2_bf16(float x, float y, uint32_t& hi, uint32_t& lo) {
    hi = pack_bf16(x, y);
    float rx = x - __uint_as_float(hi << 16);
    float ry = y - __uint_as_float(hi & 0xffff0000u);
    lo = pack_bf16(rx, ry);
}

// mma.sync m16n8k16 bf16 (baseline PTX)
__device__ __forceinline__ void mma_bf16(float* c, const uint32_t* a,
                                         uint32_t b0, uint32_t b1) {
    asm volatile(
        "mma.sync.aligned.m16n8k16.row.col.f32.bf16.bf16.f32 "
        "{%0,%1,%2,%3}, {%4,%5,%6,%7}, {%8,%9}, {%0,%1,%2,%3};"
        : "+f"(c[0]), "+f"(c[1]), "+f"(c[2]), "+f"(c[3])
        : "r"(a[0]), "r"(a[1]), "r"(a[2]), "r"(a[3]), "r"(b0), "r"(b1));
}

// SMEM layout for k_mma (dynamic) — same as round 8
#define MM_ROWMAP 0
#define MM_ASH    512
#define MM_ASL    18944
#define MM_BSH    37376
#define MM_BSL    55808
#define MM_TOT    74240
#define WP 36
#define CP 132

// ---------------- prep kernels ----------------------------------------------
// dense weight W[K=128][N=128] fp32 -> n-major bf16 hi/lo planes [n][64 kp]
__global__ void prep_w(const float* __restrict__ W, long long sW,
                       uint32_t* __restrict__ Bh, uint32_t* __restrict__ Bl) {
    const float* Wz = W + (long long)blockIdx.y * sW;
    uint32_t* bh = Bh + (long long)blockIdx.y * 8192;
    uint32_t* bl = Bl + (long long)blockIdx.y * 8192;
    for (int id = threadIdx.x; id < 8192; id += 256) {
        int kp = id >> 7, n = id & 127;        // coalesced loads over n
        float x = Wz[(2 * kp) * 128 + n];
        float y = Wz[(2 * kp + 1) * 128 + n];
        uint32_t h, l;
        split2_bf16(x, y, h, l);
        bh[n * 64 + kp] = h;
        bl[n * 64 + kp] = l;
    }
}

// rel_att[r][H][DK][DK] -> dense block-diagonal n-major planes
__global__ void prep_rel(const float* __restrict__ rel,
                         uint32_t* __restrict__ Bh, uint32_t* __restrict__ Bl) {
    int r = blockIdx.y;
    const float* R = rel + r * 4096;
    uint32_t* bh = Bh + (long long)r * 8192;
    uint32_t* bl = Bl + (long long)r * 8192;
    for (int id = threadIdx.x; id < 8192; id += 256) {
        int kp = id >> 7, n = id & 127;
        int hn = n >> 5, dm = n & 31;
        int k0 = 2 * kp, k1 = 2 * kp + 1;
        float x = ((k0 >> 5) == hn) ? R[hn * 1024 + (k0 & 31) * 32 + dm] : 0.0f;
        float y = ((k1 >> 5) == hn) ? R[hn * 1024 + (k1 & 31) * 32 + dm] : 0.0f;
        uint32_t h, l;
        split2_bf16(x, y, h, l);
        bh[n * 64 + kp] = h;
        bl[n * 64 + kp] = l;
    }
}

// split row-major fp32 matrix [N][128] into hi/lo pair planes [N][64]
__global__ void prep_rows(const float* __restrict__ A,
                          uint32_t* __restrict__ Ah, uint32_t* __restrict__ Al) {
    int id = blockIdx.x * 256 + threadIdx.x;
    if (id >= Nn * 64) return;
    int n = id >> 6, kp = id & 63;
    float2 v = *(const float2*)&A[(long long)n * 128 + 2 * kp];
    uint32_t h, l;
    split2_bf16(v.x, v.y, h, l);
    Ah[id] = h;
    Al[id] = l;
}

// ---------------- unified bf16x3 mma GEMM -----------------------------------
// modes: 0 = dense (z-batched fp32 A / C), 1 = typed via g_perm (z = type)
// If Aph != nullptr, A comes from pre-split planes (row stride 64, z stride sAp).
// B always from pre-split planes (z stride sBp, in uint32 units).
__global__ void __launch_bounds__(256) k_mma(
    const float* __restrict__ Ab, long long sA,
    const uint32_t* __restrict__ Aph, const uint32_t* __restrict__ Apl, long long sAp,
    const uint32_t* __restrict__ Bph, const uint32_t* __restrict__ Bpl, long long sBp,
    const float* __restrict__ biasb, long long sBias,
    float* __restrict__ Cb, long long sC,
    int M, int mode)
{
    extern __shared__ char smem[];
    int* rowmap = (int*)(smem + MM_ROWMAP);
    uint32_t* Ash = (uint32_t*)(smem + MM_ASH);
    uint32_t* Asl = (uint32_t*)(smem + MM_ASL);
    uint32_t* Bsh = (uint32_t*)(smem + MM_BSH);
    uint32_t* Bsl = (uint32_t*)(smem + MM_BSL);
    float* Cs = (float*)(smem + MM_ASH);   // reuse after compute

    int tid = threadIdx.x;
    int lane = tid & 31;
    int warp = tid >> 5;
    int warpM = warp >> 1, warpN = warp & 1;
    int g8 = lane >> 2, t4 = lane & 3;
    int z = blockIdx.y;

    const float* A = Ab;
    const uint32_t* Ah = Aph ? Aph + (long long)z * sAp : nullptr;
    const uint32_t* Al = Apl ? Apl + (long long)z * sAp : nullptr;
    const uint32_t* Bh = Bph + (long long)z * sBp;
    const uint32_t* Bl = Bpl + (long long)z * sBp;
    const float* bias = nullptr;
    float* C = Cb;
    int row0, rend;
    if (mode == 0) {
        if (Ab) A += (long long)z * sA;
        C += (long long)z * sC;
        if (biasb) bias = biasb + (long long)z * sBias;
        row0 = blockIdx.x * 128; rend = M;
        if (row0 >= M) return;
    } else {
        if (biasb) bias = biasb + (long long)z * sBias;
        row0 = g_toff[z] + blockIdx.x * 128; rend = g_toff[z + 1];
        if (row0 >= rend) return;
    }

    if (tid < 128) {
        int gr = row0 + tid;
        int node = -1;
        if (gr < rend) node = (mode == 1) ? g_perm[gr] : gr;
        rowmap[tid] = node;
    }

    float acc[2][8][4];
#pragma unroll
    for (int mt = 0; mt < 2; mt++)
#pragma unroll
        for (int nt = 0; nt < 8; nt++)
#pragma unroll
            for (int c = 0; c < 4; c++) acc[mt][nt][c] = 0.0f;

#pragma unroll 1
    for (int kb = 0; kb < 2; kb++) {
        __syncthreads();
        // ---- stage A ----
        if (Ah) {
#pragma unroll
            for (int j = 0; j < 8; j++) {
                int id = tid + 256 * j;          // 2048 uint2 (128 rows x 16)
                int r = id >> 4, kp2 = id & 15;
                int node = rowmap[r];
                uint2 vh = make_uint2(0, 0), vl = make_uint2(0, 0);
                if (node >= 0) {
                    long long src = (long long)node * 64 + kb * 32 + kp2 * 2;
                    vh = *(const uint2*)&Ah[src];
                    vl = *(const uint2*)&Al[src];
                }
                *(uint2*)&Ash[r * WP + kp2 * 2] = vh;
                *(uint2*)&Asl[r * WP + kp2 * 2] = vl;
            }
        } else {
#pragma unroll
            for (int j = 0; j < 8; j++) {
                int id = tid + 256 * j;          // 2048 float4
                int r = id >> 4, k4 = id & 15;
                int node = rowmap[r];
                float4 v = make_float4(0.f, 0.f, 0.f, 0.f);
                if (node >= 0) v = *(const float4*)&A[(long long)node * 128 + kb * 64 + k4 * 4];
                uint32_t h01, l01, h23, l23;
                split2_bf16(v.x, v.y, h01, l01);
                split2_bf16(v.z, v.w, h23, l23);
                *(uint2*)&Ash[r * WP + k4 * 2] = make_uint2(h01, h23);
                *(uint2*)&Asl[r * WP + k4 * 2] = make_uint2(l01, l23);
            }
        }
        // ---- stage B (pre-split planes, plain copy) ----
#pragma unroll
        for (int j = 0; j < 8; j++) {
            int id = tid + 256 * j;              // 2048 uint2
            int n = id >> 4, kp2 = id & 15;
            long long src = (long long)n * 64 + kb * 32 + kp2 * 2;
            uint2 vh = *(const uint2*)&Bh[src];
            uint2 vl = *(const uint2*)&Bl[src];
            *(uint2*)&Bsh[n * WP + kp2 * 2] = vh;
            *(uint2*)&Bsl[n * WP + kp2 * 2] = vl;
        }
        __syncthreads();

        // ---- compute: 4 k16-steps, 3xBF16 ----
#pragma unroll
        for (int ks = 0; ks < 4; ks++) {
            int ub = ks * 8 + t4;
            uint32_t ah[2][4], al[2][4];
#pragma unroll
            for (int mt = 0; mt < 2; mt++) {
                int rb = warpM * 32 + mt * 16 + g8;
                int base = rb * WP + ub;
                ah[mt][0] = Ash[base];
                ah[mt][1] = Ash[base + 8 * WP];
                ah[mt][2] = Ash[base + 4];
                ah[mt][3] = Ash[base + 8 * WP + 4];
                al[mt][0] = Asl[base];
                al[mt][1] = Asl[base + 8 * WP];
                al[mt][2] = Asl[base + 4];
                al[mt][3] = Asl[base + 8 * WP + 4];
            }
#pragma unroll
            for (int nt = 0; nt < 8; nt++) {
                int nb = warpN * 64 + nt * 8 + g8;
                int bbase = nb * WP + ub;
                uint32_t bh0 = Bsh[bbase], bh1 = Bsh[bbase + 4];
                uint32_t bl0 = Bsl[bbase], bl1 = Bsl[bbase + 4];
                mma_bf16(acc[0][nt], ah[0], bh0, bh1);
                mma_bf16(acc[1][nt], ah[1], bh0, bh1);
                mma_bf16(acc[0][nt], ah[0], bl0, bl1);
                mma_bf16(acc[1][nt], ah[1], bl0, bl1);
                mma_bf16(acc[0][nt], al[0], bh0, bh1);
                mma_bf16(acc[1][nt], al[1], bh0, bh1);
            }
        }
    }

    // ---- epilogue: acc -> Cs (staged) -> coalesced GMEM ----
    __syncthreads();
#pragma unroll
    for (int mt = 0; mt < 2; mt++) {
        int r0 = warpM * 32 + mt * 16 + g8;
#pragma unroll
        for (int nt = 0; nt < 8; nt++) {
            int cc = warpN * 64 + nt * 8 + 2 * t4;
            Cs[r0 * CP + cc]           = acc[mt][nt][0];
            Cs[r0 * CP + cc + 1]       = acc[mt][nt][1];
            Cs[(r0 + 8) * CP + cc]     = acc[mt][nt][2];
            Cs[(r0 + 8) * CP + cc + 1] = acc[mt][nt][3];
        }
    }
    __syncthreads();
#pragma unroll
    for (int j = 0; j < 16; j++) {
        int id = tid + 256 * j;                  // 4096 float4 slots
        int r = id >> 5, c4 = id & 31;
        int node = rowmap[r];
        if (node >= 0) {
            float4 v = *(const float4*)&Cs[r * CP + c4 * 4];
            if (bias) {
                v.x += bias[c4 * 4 + 0]; v.y += bias[c4 * 4 + 1];
                v.z += bias[c4 * 4 + 2]; v.w += bias[c4 * 4 + 3];
            }
            *(float4*)&C[(long long)node * 128 + c4 * 4] = v;
        }
    }
}

// ---------------- setup ----------------
__global__ void k_init() {
    int tid = blockIdx.x * 256 + threadIdx.x;
    if (tid < NH) { g_mx[tid] = __int_as_float(0xff800000); g_den[tid] = 0.0f; }
    if (tid < Nn) g_deg[tid] = 0;
    if (tid < Tt) { g_tcount[tid] = 0; g_cursor[tid] = 0; }
}
__global__ void k_count(const int* __restrict__ node_type, const int* __restrict__ ei) {
    int tid = blockIdx.x * 256 + threadIdx.x;
    if (tid < Nn) atomicAdd(&g_tcount[node_type[tid]], 1);
    if (tid < Ee) atomicAdd(&g_deg[ei[Ee + tid]], 1);
}
__global__ void k_scan() {
    if (threadIdx.x == 0 && blockIdx.x == 0) {
        g_toff[0] = 0;
        for (int t = 0; t < Tt; t++) g_toff[t + 1] = g_toff[t] + g_tcount[t];
    }
}
__global__ void k_scatter(const int* __restrict__ node_type) {
    int tid = blockIdx.x * 256 + threadIdx.x;
    if (tid < Nn) {
        int t = node_type[tid];
        int pos = g_toff[t] + atomicAdd(&g_cursor[t], 1);
        g_perm[pos] = tid;
    }
}

// ---------------- FFMA2 GEMM (tiny wcomb only) ------------------------------
#define GEMM_INNER(AS, BS)                                                   \
    _Pragma("unroll")                                                        \
    for (int k = 0; k < 32; k++) {                                           \
        const float4 av = *(const float4*)&AS;                               \
        ull a0 = dup2(av.x), a1 = dup2(av.y), a2 = dup2(av.z), a3 = dup2(av.w); \
        _Pragma("unroll")                                                    \
        for (int j4 = 0; j4 < 4; j4++) {                                     \
            const float4 bv = *(const float4*)&BS;                           \
            ull b0 = pack2(bv.x, bv.y), b1 = pack2(bv.z, bv.w);              \
            fma2(acc[0][2*j4], a0, b0); fma2(acc[0][2*j4+1], a0, b1);        \
            fma2(acc[1][2*j4], a1, b0); fma2(acc[1][2*j4+1], a1, b1);        \
            fma2(acc[2][2*j4], a2, b0); fma2(acc[2][2*j4+1], a2, b1);        \
            fma2(acc[3][2*j4], a3, b0); fma2(acc[3][2*j4+1], a3, b1);        \
        }                                                                    \
    }

__global__ void __launch_bounds__(256) k_gemm2(
    const float* __restrict__ Ab, long long sA,
    const float* __restrict__ Bb, long long sB,
    const float* __restrict__ biasb, long long sBias,
    float* __restrict__ Cb, long long sC, int M)
{
    const float* A = Ab + (long long)blockIdx.z * sA;
    const float* B = Bb + (long long)blockIdx.z * sB;
    const float* bias = biasb ? (biasb + (long long)blockIdx.z * sBias) : nullptr;
    float* C = Cb + (long long)blockIdx.z * sC;
    int row0 = blockIdx.x * 128;
    if (row0 >= M) return;

    __shared__ float Bs[32][132];
    __shared__ float AsT[32][132];
    int tid = threadIdx.x;
    int tr = tid >> 3, tc = tid & 7;

    ull acc[4][8];
#pragma unroll
    for (int i = 0; i < 4; i++)
#pragma unroll
        for (int j = 0; j < 8; j++) acc[i][j] = 0ULL;

#pragma unroll 1
    for (int kc = 0; kc < 4; kc++) {
        __syncthreads();
#pragma unroll
        for (int j = 0; j < 4; j++) {
            int id = tid + 256 * j;
            int brow = id >> 5, bc = id & 31;
            float4 v = *(const float4*)&B[(kc * 32 + brow) * 128 + bc * 4];
            *(float4*)&Bs[brow][(bc & 3) * 32 + (bc >> 2) * 4] = v;
        }
#pragma unroll
        for (int j = 0; j < 4; j++) {
            int id = tid + 256 * j;
            int arow = id >> 3, a4 = id & 7;
            int grow = row0 + arow;
            float4 v = make_float4(0.f, 0.f, 0.f, 0.f);
            if (grow < M) v = *(const float4*)&A[(long long)grow * 128 + kc * 32 + a4 * 4];
            AsT[a4 * 4 + 0][arow] = v.x;
            AsT[a4 * 4 + 1][arow] = v.y;
            AsT[a4 * 4 + 2][arow] = v.z;
            AsT[a4 * 4 + 3][arow] = v.w;
        }
        __syncthreads();
        GEMM_INNER(AsT[k][tr * 4], Bs[k][j4 * 32 + tc * 4])
    }

#pragma unroll
    for (int i = 0; i < 4; i++) {
        int grow = row0 + tr * 4 + i;
        if (grow < M) {
#pragma unroll
            for (int j4 = 0; j4 < 4; j4++) {
                float2 u0 = unpack2(acc[i][2 * j4]);
                float2 u1 = unpack2(acc[i][2 * j4 + 1]);
                int col = tc * 16 + j4 * 4;
                float4 o = make_float4(u0.x, u0.y, u1.x, u1.y);
                if (bias) {
                    o.x += bias[col]; o.y += bias[col + 1];
                    o.z += bias[col + 2]; o.w += bias[col + 3];
                }
                *(float4*)&C[(long long)grow * 128 + col] = o;
            }
        }
    }
}

// ---------------- edge logits + segment max ---------------------------------
__global__ void __launch_bounds__(256) k_logits(
    const int* __restrict__ ei, const int* __restrict__ et,
    const float* __restrict__ rel_pri)
{
    int warp = threadIdx.x >> 5, lane = threadIdx.x & 31;
    int w = blockIdx.x * 8 + warp;
    int stride = gridDim.x * 8;
    for (int e = w; e < Ee; e += stride) {
        int s = ei[e], t = ei[Ee + e], r = et[e];
        const float* q = g_qn + (long long)t * 128;
        const float* kk = g_knr + ((long long)r * Nn + s) * 128;
        float q0 = q[lane], q1 = q[32 + lane], q2 = q[64 + lane], q3 = q[96 + lane];
        float k0 = kk[lane], k1 = kk[32 + lane], k2 = kk[64 + lane], k3 = kk[96 + lane];
        float p0 = q0 * k0, p1 = q1 * k1, p2 = q2 * k2, p3 = q3 * k3;
#pragma unroll
        for (int o = 16; o > 0; o >>= 1) {
            p0 += __shfl_xor_sync(0xffffffffu, p0, o);
            p1 += __shfl_xor_sync(0xffffffffu, p1, o);
            p2 += __shfl_xor_sync(0xffffffffu, p2, o);
            p3 += __shfl_xor_sync(0xffffffffu, p3, o);
        }
        if (lane < 4) {
            float pv = (lane == 0) ? p0 : (lane == 1) ? p1 : (lane == 2) ? p2 : p3;
            float lg = pv * rel_pri[r * 4 + lane] * 0.17677669529663687f;
            g_ex[e * 4 + lane] = lg;
            atomicMaxF(&g_mx[t * 4 + lane], lg);
        }
    }
}

// ---------------- exp + denominator (vectorized: one thread per edge) -------
__global__ void k_expden4(const int* __restrict__ ei) {
    int e = blockIdx.x * 256 + threadIdx.x;
    if (e >= Ee) return;
    int t = ei[Ee + e];
    float4 lg = *(const float4*)&g_ex[e * 4];
    float4 m = *(const float4*)&g_mx[t * 4];
    float4 v;
    v.x = expf(lg.x - m.x);
    v.y = expf(lg.y - m.y);
    v.z = expf(lg.z - m.z);
    v.w = expf(lg.w - m.w);
    *(float4*)&g_ex[e * 4] = v;
    atomicAdd(&g_den[t * 4 + 0], v.x);
    atomicAdd(&g_den[t * 4 + 1], v.y);
    atomicAdd(&g_den[t * 4 + 2], v.z);
    atomicAdd(&g_den[t * 4 + 3], v.w);
}

// ---------------- messages (only edge ids < N matter) -----------------------
__global__ void __launch_bounds__(256) k_msg(
    const int* __restrict__ ei, const int* __restrict__ et,
    const float* __restrict__ rel_msg)
{
    extern __shared__ float sh[];
    float* relS = sh;
    float* vnS = sh + RELF;
    for (int i = threadIdx.x; i < RELF; i += 256) relS[i] = rel_msg[i];
    __syncthreads();

    int warp = threadIdx.x >> 5, lane = threadIdx.x & 31;
    float* vW = vnS + warp * 128;
    int stride = gridDim.x * 8;
    for (int n = blockIdx.x * 8 + warp; n < Nn; n += stride) {
        int s = ei[n], t = ei[Ee + n], r = et[n];
        __syncwarp();
#pragma unroll
        for (int h = 0; h < 4; h++)
            vW[h * 32 + lane] = g_vn[(long long)s * 128 + h * 32 + lane];
        __syncwarp();
        float deg = (float)g_deg[n];
#pragma unroll
        for (int h = 0; h < 4; h++) {
            float att = g_ex[n * 4 + h] / (g_den[t * 4 + h] + 1e-16f);
            const float* Am = relS + (r * 4 + h) * 1024;
            float a0 = 0.f, a1 = 0.f;
#pragma unroll
            for (int d = 0; d < 32; d += 2) {
                a0 = fmaf(vW[h * 32 + d],     Am[d * 32 + lane],       a0);
                a1 = fmaf(vW[h * 32 + d + 1], Am[(d + 1) * 32 + lane], a1);
            }
            float vp = a0 + a1;
            float c = att * deg;
            long long o = (long long)n * 128 + h * 32 + lane;
            float m1 = vp * c;
            float m2 = vp * vp * c;
            float m3 = vp * vp * vp * c;
            float s3 = (m3 > 0.f) ? 1.f : ((m3 < 0.f) ? -1.f : 0.f);
            float r3 = s3 * powf(fabsf(m3) + 1e-18f, 0.33333333333333333f);
            g_agg[o] = m1;
            g_agg[ND + o] = m2;
            g_agg[2 * ND + o] = r3;
        }
    }
}

// ---------------- bfront[k] = bq @ Wak[k] -----------------------------------
__global__ void k_bfront(const float* __restrict__ Wak, const float* __restrict__ bq) {
    int kk = blockIdx.x, j = threadIdx.x;
    float s = 0.f;
#pragma unroll 4
    for (int d = 0; d < 128; d++)
        s = fmaf(bq[d], Wak[kk * 16384 + d * 128 + j], s);
    g_bfront[kk * 128 + j] = s;
}

// ---------------- gating + residual + gelu ----------------------------------
__global__ void __launch_bounds__(256) k_res() {
    int warp = threadIdx.x >> 5, lane = threadIdx.x & 31;
    int n = blockIdx.x * 8 + warp;
    if (n >= Nn) return;
    long long base = (long long)n * 128 + lane * 4;
    float r0 = 0.f, r1 = 0.f, r2 = 0.f, r3 = 0.f;
#pragma unroll
    for (int kk = 0; kk < 3; kk++) {
        const float4 f = *(const float4*)&g_front[kk * ND + base];
        const float4 t4 = *(const float4*)&g_tail[kk * ND + base];
        float p = f.x * t4.x + f.y * t4.y + f.z * t4.z + f.w * t4.w;
#pragma unroll
        for (int o = 16; o > 0; o >>= 1) p += __shfl_xor_sync(0xffffffffu, p, o);
        float tt = sigmoidf_(p);
        const float4 am = *(const float4*)&g_aggm[kk * ND + base];
        r0 = fmaf(tt, am.x, r0);
        r1 = fmaf(tt, am.y, r1);
        r2 = fmaf(tt, am.z, r2);
        r3 = fmaf(tt, am.w, r3);
    }
    float4 o;
    o.x = 0.5f * r0 * (1.0f + erff(r0 * 0.70710678118654752f));
    o.y = 0.5f * r1 * (1.0f + erff(r1 * 0.70710678118654752f));
    o.z = 0.5f * r2 * (1.0f + erff(r2 * 0.70710678118654752f));
    o.w = 0.5f * r3 * (1.0f + erff(r3 * 0.70710678118654752f));
    *(float4*)&g_hbuf[base] = o;
}

// ---------------- skip-mix + per-type LayerNorm -----------------------------
__global__ void __launch_bounds__(256) k_final(
    const float* __restrict__ meta, const int* __restrict__ node_type,
    const float* __restrict__ skip, const float* __restrict__ ln_g,
    const float* __restrict__ ln_b, float* __restrict__ out)
{
    int warp = threadIdx.x >> 5, lane = threadIdx.x & 31;
    int n = blockIdx.x * 8 + warp;
    if (n >= Nn) return;
    int t = node_type[n];
    float alpha = sigmoidf_(skip[t]);
    long long base = (long long)n * 128 + lane * 4;
    const float4 tr = *(const float4*)&g_trans[base];
    const float4 x = *(const float4*)&meta[base];
    float y0 = tr.x * alpha + x.x * (1.0f - alpha);
    float y1 = tr.y * alpha + x.y * (1.0f - alpha);
    float y2 = tr.z * alpha + x.z * (1.0f - alpha);
    float y3 = tr.w * alpha + x.w * (1.0f - alpha);
    float s = y0 + y1 + y2 + y3;
    float sq = y0 * y0 + y1 * y1 + y2 * y2 + y3 * y3;
#pragma unroll
    for (int o = 16; o > 0; o >>= 1) {
        s += __shfl_xor_sync(0xffffffffu, s, o);
        sq += __shfl_xor_sync(0xffffffffu, sq, o);
    }
    float mu = s * (1.0f / 128.0f);
    float var = sq * (1.0f / 128.0f) - mu * mu;
    float inv = 1.0f / sqrtf(var + 1e-5f);
    int c = lane * 4;
    const float4 g = *(const float4*)&ln_g[t * 128 + c];
    const float4 b = *(const float4*)&ln_b[t * 128 + c];
    float4 o;
    o.x = (y0 - mu) * inv * g.x + b.x;
    o.y = (y1 - mu) * inv * g.y + b.y;
    o.z = (y2 - mu) * inv * g.z + b.z;
    o.w = (y3 - mu) * inv * g.w + b.w;
    *(float4*)&out[base] = o;
}

// ---------------- host launcher ---------------------------------------------
extern "C" void kernel_launch(void* const* d_in, const int* in_sizes, int n_in,
                              void* d_out, int out_size)
{
    const float* meta      = (const float*)d_in[0];
    const int*   node_type = (const int*)d_in[1];
    const int*   ei        = (const int*)d_in[2];
    const int*   etype     = (const int*)d_in[3];
    const float* q_w = (const float*)d_in[5];
    const float* q_b = (const float*)d_in[6];
    const float* k_w = (const float*)d_in[7];
    const float* k_b = (const float*)d_in[8];
    const float* v_w = (const float*)d_in[9];
    const float* v_b = (const float*)d_in[10];
    const float* a_w = (const float*)d_in[11];
    const float* a_b = (const float*)d_in[12];
    const float* rel_pri = (const float*)d_in[13];
    const float* rel_att = (const float*)d_in[14];
    const float* rel_msg = (const float*)d_in[15];
    const float* WMk = (const float*)d_in[16];
    const float* Wak = (const float*)d_in[17];
    const float* Wq  = (const float*)d_in[18];
    const float* bq  = (const float*)d_in[19];
    const float* Wkl = (const float*)d_in[20];
    const float* bkl = (const float*)d_in[21];
    const float* skip = (const float*)d_in[22];
    const float* ln_g = (const float*)d_in[23];
    const float* ln_b = (const float*)d_in[24];
    float* out = (float*)d_out;

    float *p_qn, *p_kn, *p_vn, *p_knr, *p_agg, *p_aggm, *p_front, *p_tail,
          *p_hbuf, *p_trans, *p_wcomb, *p_bfront;
    uint32_t *p_bsh, *p_bsl, *p_metah, *p_metal, *p_knh, *p_knl;
    cudaGetSymbolAddress((void**)&p_qn, g_qn);
    cudaGetSymbolAddress((void**)&p_kn, g_kn);
    cudaGetSymbolAddress((void**)&p_vn, g_vn);
    cudaGetSymbolAddress((void**)&p_knr, g_knr);
    cudaGetSymbolAddress((void**)&p_agg, g_agg);
    cudaGetSymbolAddress((void**)&p_aggm, g_aggm);
    cudaGetSymbolAddress((void**)&p_front, g_front);
    cudaGetSymbolAddress((void**)&p_tail, g_tail);
    cudaGetSymbolAddress((void**)&p_hbuf, g_hbuf);
    cudaGetSymbolAddress((void**)&p_trans, g_trans);
    cudaGetSymbolAddress((void**)&p_wcomb, g_wcomb);
    cudaGetSymbolAddress((void**)&p_bfront, g_bfront);
    cudaGetSymbolAddress((void**)&p_bsh, g_bsh);
    cudaGetSymbolAddress((void**)&p_bsl, g_bsl);
    cudaGetSymbolAddress((void**)&p_metah, g_metah);
    cudaGetSymbolAddress((void**)&p_metal, g_metal);
    cudaGetSymbolAddress((void**)&p_knh, g_knh);
    cudaGetSymbolAddress((void**)&p_knl, g_knl);

    const int SMEM_EDGE = (RELF + 8 * 128) * 4;               // 86016 B
    cudaFuncSetAttribute(k_msg, cudaFuncAttributeMaxDynamicSharedMemorySize, SMEM_EDGE);
    cudaFuncSetAttribute(k_mma, cudaFuncAttributeMaxDynamicSharedMemorySize, MM_TOT);

    dim3 blk(256);
    const int GB = 313;   // ceil(40000/128)
    const int PR = (Nn * 64 + 255) / 256;  // prep_rows grid

    k_init<<<625, blk>>>();
    k_count<<<1250, blk>>>(node_type, ei);
    k_scan<<<1, 32>>>();
    k_scatter<<<157, blk>>>(node_type);

    // pre-split weights into bf16 planes
    prep_w<<<dim3(1, 3), blk>>>(q_w, 16384, p_bsh + 0 * 8192, p_bsl + 0 * 8192);
    prep_w<<<dim3(1, 3), blk>>>(k_w, 16384, p_bsh + 3 * 8192, p_bsl + 3 * 8192);
    prep_w<<<dim3(1, 3), blk>>>(v_w, 16384, p_bsh + 6 * 8192, p_bsl + 6 * 8192);
    prep_w<<<dim3(1, 3), blk>>>(a_w, 16384, p_bsh + 9 * 8192, p_bsl + 9 * 8192);
    prep_w<<<dim3(1, 3), blk>>>(WMk, 16384, p_bsh + 12 * 8192, p_bsl + 12 * 8192);
    prep_w<<<dim3(1, 1), blk>>>(Wkl, 0, p_bsh + 18 * 8192, p_bsl + 18 * 8192);
    prep_rel<<<dim3(1, 5), blk>>>(rel_att, p_bsh + 19 * 8192, p_bsl + 19 * 8192);
    prep_rows<<<PR, blk>>>(meta, p_metah, p_metal);

    // typed q/k/v projections (bf16x3, A = pre-split meta planes)
    k_mma<<<dim3(GB, 3), blk, MM_TOT>>>(nullptr, 0, p_metah, p_metal, 0,
        p_bsh + 0 * 8192, p_bsl + 0 * 8192, 8192, q_b, 128, p_qn, 0, Nn, 1);
    k_mma<<<dim3(GB, 3), blk, MM_TOT>>>(nullptr, 0, p_metah, p_metal, 0,
        p_bsh + 3 * 8192, p_bsl + 3 * 8192, 8192, k_b, 128, p_kn, 0, Nn, 1);
    k_mma<<<dim3(GB, 3), blk, MM_TOT>>>(nullptr, 0, p_metah, p_metal, 0,
        p_bsh + 6 * 8192, p_bsl + 6 * 8192, 8192, v_b, 128, p_vn, 0, Nn, 1);

    // fold qlin: Wcomb[k] = Wq @ Wak[k]; bfront[k] = bq @ Wak[k]
    k_gemm2<<<dim3(1, 1, 3), blk>>>(Wq, 0, Wak, 16384, nullptr, 0, p_wcomb, 16384, 128);
    k_bfront<<<3, 128>>>(Wak, bq);
    prep_w<<<dim3(1, 3), blk>>>(p_wcomb, 16384, p_bsh + 15 * 8192, p_bsl + 15 * 8192);

    // pre-split kn, then knr[r] = kn @ blockdiag(rel_att[r]) as dense GEMM
    prep_rows<<<PR, blk>>>(p_kn, p_knh, p_knl);
    k_mma<<<dim3(GB, 5), blk, MM_TOT>>>(nullptr, 0, p_knh, p_knl, 0,
        p_bsh + 19 * 8192, p_bsl + 19 * 8192, 8192, nullptr, 0, p_knr, ND, Nn, 0);

    // logits + segment max; exp + denominators
    k_logits<<<1184, blk>>>(ei, etype, rel_pri);
    k_expden4<<<1250, blk>>>(ei);

    // messages for edge ids < N (reference aggregate quirk: deg * msg[n])
    k_msg<<<296, blk, SMEM_EDGE>>>(ei, etype, rel_msg);

    // aggm[k] = agg[k] @ WMk[k]
    k_mma<<<dim3(GB, 3), blk, MM_TOT>>>(p_agg, ND, nullptr, nullptr, 0,
        p_bsh + 12 * 8192, p_bsl + 12 * 8192, 8192, nullptr, 0, p_aggm, ND, Nn, 0);
    // front[k] = meta @ Wcomb[k] + bfront[k]
    k_mma<<<dim3(GB, 3), blk, MM_TOT>>>(nullptr, 0, p_metah, p_metal, 0,
        p_bsh + 15 * 8192, p_bsl + 15 * 8192, 8192, p_bfront, 128, p_front, ND, Nn, 0);
    // tail[k] = aggm[k] @ Wkl + bkl
    k_mma<<<dim3(GB, 3), blk, MM_TOT>>>(p_aggm, ND, nullptr, nullptr, 0,
        p_bsh + 18 * 8192, p_bsl + 18 * 8192, 0, bkl, 0, p_tail, ND, Nn, 0);

    k_res<<<5000, blk>>>();

    // trans = typed(gelu(res), a_w, a_b)
    k_mma<<<dim3(GB, 3), blk, MM_TOT>>>(p_hbuf, 0, nullptr, nullptr, 0,
        p_bsh + 9 * 8192, p_bsl + 9 * 8192, 8192, a_b, 128, p_trans, 0, Nn, 1);

    k_final<<<5000, blk>>>(meta, node_type, skip, ln_g, ln_b, out);
}

// round 12
// speedup vs baseline: 1.5286x; 1.5286x over previous
#include <cuda_runtime.h>
#include <cuda_bf16.h>
#include <math.h>
#include <stdint.h>

#define Nn 40000
#define Ee 320000
#define Dd 128
#define Hh 4
#define DK 32
#define Tt 3
#define Rr 5
#define Kk 3
#define ND 5120000      // N*D
#define EH 1280000      // E*H
#define NH 160000       // N*H
#define RELF 20480      // R*H*DK*DK floats

typedef unsigned long long ull;

// ---------------- device scratch ----------------
__device__ __align__(16) float g_qn[ND];
__device__ __align__(16) float g_kn[ND];
__device__ __align__(16) float g_vn[ND];
__device__ __align__(16) float g_knr[Rr * ND];   // [r][n][128]
__device__ __align__(16) float g_ex[EH];
__device__ __align__(16) float g_mx[NH];
__device__ __align__(16) float g_den[NH];
__device__ int   g_deg[Nn];
__device__ int   g_perm[Nn];
__device__ int   g_tcount[Tt];
__device__ int   g_toff[Tt + 1];
__device__ int   g_cursor[Tt];
__device__ __align__(16) float g_agg[Kk * ND];
__device__ __align__(16) float g_aggm[Kk * ND];
__device__ __align__(16) float g_front[Kk * ND];
__device__ __align__(16) float g_tail[Kk * ND];
__device__ __align__(16) float g_hbuf[ND];
__device__ __align__(16) float g_trans[ND];
__device__ __align__(16) float g_wcomb[Kk * 16384];
__device__ __align__(16) float g_bfront[Kk * 128];

// ---------------- small helpers ----------------
__device__ __forceinline__ float sigmoidf_(float x) { return 1.0f / (1.0f + expf(-x)); }

__device__ __forceinline__ void atomicMaxF(float* addr, float v) {
    int old = __float_as_int(*addr);
    while (__int_as_float(old) < v) {
        int prev = atomicCAS((int*)addr, old, __float_as_int(v));
        if (prev == old) break;
        old = prev;
    }
}

__device__ __forceinline__ void fma2(ull& d, ull a, ull b) {
    asm("fma.rn.f32x2 %0, %1, %2, %0;" : "+l"(d) : "l"(a), "l"(b));
}
__device__ __forceinline__ ull dup2(float x) {
    ull r; asm("mov.b64 %0, {%1, %1};" : "=l"(r) : "f"(x)); return r;
}
__device__ __forceinline__ ull pack2(float x, float y) {
    ull r; asm("mov.b64 %0, {%1, %2};" : "=l"(r) : "f"(x), "f"(y)); return r;
}
__device__ __forceinline__ float2 unpack2(ull v) {
    float2 f; asm("mov.b64 {%0, %1}, %2;" : "=f"(f.x), "=f"(f.y) : "l"(v)); return f;
}

// pack two floats to bf16x2 (low = x, high = y), round-to-nearest
__device__ __forceinline__ uint32_t pack_bf16(float x, float y) {
    uint32_t r; asm("cvt.rn.bf16x2.f32 %0, %1, %2;" : "=r"(r) : "f"(y), "f"(x));
    return r;
}
// split pair (x,y) into hi bf16x2 + lo bf16x2 (residual)
__device__ __forceinline__ void split2_bf16(float x, float y, uint32_t& hi, uint32_t& lo) {
    hi = pack_bf16(x, y);
    float rx = x - __uint_as_float(hi << 16);
    float ry = y - __uint_as_float(hi & 0xffff0000u);
    lo = pack_bf16(rx, ry);
}

// mma.sync m16n8k16 bf16 (baseline PTX)
__device__ __forceinline__ void mma_bf16(float* c, const uint32_t* a,
                                         uint32_t b0, uint32_t b1) {
    asm volatile(
        "mma.sync.aligned.m16n8k16.row.col.f32.bf16.bf16.f32 "
        "{%0,%1,%2,%3}, {%4,%5,%6,%7}, {%8,%9}, {%0,%1,%2,%3};"
        : "+f"(c[0]), "+f"(c[1]), "+f"(c[2]), "+f"(c[3])
        : "r"(a[0]), "r"(a[1]), "r"(a[2]), "r"(a[3]), "r"(b0), "r"(b1));
}

// SMEM layout for k_mma (dynamic):
//  [0:512)          rowmap (128 ints)
//  [512:   +18432)  As_hi [128][36] uint  (bf16x2 pairs along K; 32 used + 4 pad)
//  [18944: +18432)  As_lo
//  [37376: +18432)  Bs_hi [128][36] uint  (n-major: Bs[n][k-pairs])
//  [55808: +18432)  Bs_lo
//  Cs overlaps As_* at [512: +67584) = [128][132] floats for epilogue staging
#define MM_ROWMAP 0
#define MM_ASH    512
#define MM_ASL    18944
#define MM_BSH    37376
#define MM_BSL    55808
#define MM_TOT    74240
#define WP 36
#define CP 132

// ---------------- unified bf16x3 mma GEMM -----------------------------------
// modes: 0 = dense (z-batched A/W/bias/C), 1 = typed via g_perm (z = type),
//        2 = block-diag rel (W = rel[z], B block-diagonal per head)
__global__ void __launch_bounds__(256) k_mma(
    const float* __restrict__ Ab, long long sA,
    const float* __restrict__ Wb, long long sW,
    const float* __restrict__ biasb, long long sBias,
    float* __restrict__ Cb, long long sC,
    int M, int mode)
{
    extern __shared__ char smem[];
    int* rowmap = (int*)(smem + MM_ROWMAP);
    uint32_t* Ash = (uint32_t*)(smem + MM_ASH);
    uint32_t* Asl = (uint32_t*)(smem + MM_ASL);
    uint32_t* Bsh = (uint32_t*)(smem + MM_BSH);
    uint32_t* Bsl = (uint32_t*)(smem + MM_BSL);
    float* Cs = (float*)(smem + MM_ASH);   // reuse after compute

    int tid = threadIdx.x;
    int lane = tid & 31;
    int warp = tid >> 5;
    int warpM = warp >> 1, warpN = warp & 1;
    int g8 = lane >> 2, t4 = lane & 3;
    int z = blockIdx.y;

    const float* A = Ab;
    const float* W = Wb + (long long)z * sW;
    const float* bias = nullptr;
    float* C = Cb;
    int row0, rend;
    if (mode == 0) {
        A += (long long)z * sA; C += (long long)z * sC;
        if (biasb) bias = biasb + (long long)z * sBias;
        row0 = blockIdx.x * 128; rend = M;
        if (row0 >= M) return;
    } else if (mode == 1) {
        bias = biasb + (long long)z * sBias;
        row0 = g_toff[z] + blockIdx.x * 128; rend = g_toff[z + 1];
        if (row0 >= rend) return;
    } else {
        C += (long long)z * sC;
        row0 = blockIdx.x * 128; rend = M;
        if (row0 >= M) return;
    }

    if (tid < 128) {
        int gr = row0 + tid;
        int node = -1;
        if (gr < rend) node = (mode == 1) ? g_perm[gr] : gr;
        rowmap[tid] = node;
    }

    float acc[2][8][4];
#pragma unroll
    for (int mt = 0; mt < 2; mt++)
#pragma unroll
        for (int nt = 0; nt < 8; nt++)
#pragma unroll
            for (int c = 0; c < 4; c++) acc[mt][nt][c] = 0.0f;

#pragma unroll 1
    for (int kb = 0; kb < 2; kb++) {
        __syncthreads();
        // ---- stage A rows: split to bf16 hi/lo pairs ----
#pragma unroll
        for (int j = 0; j < 8; j++) {
            int id = tid + 256 * j;              // 2048 float4 (128 rows x 16)
            int r = id >> 4, k4 = id & 15;
            int node = rowmap[r];
            float4 v = make_float4(0.f, 0.f, 0.f, 0.f);
            if (node >= 0) v = *(const float4*)&A[(long long)node * 128 + kb * 64 + k4 * 4];
            uint32_t h01, l01, h23, l23;
            split2_bf16(v.x, v.y, h01, l01);
            split2_bf16(v.z, v.w, h23, l23);
            *(uint2*)&Ash[r * WP + k4 * 2] = make_uint2(h01, h23);
            *(uint2*)&Asl[r * WP + k4 * 2] = make_uint2(l01, l23);
        }
        // ---- stage B as Bs[n][k] = W[k][n], split to bf16 hi/lo ----
        if (mode != 2) {
#pragma unroll
            for (int j = 0; j < 8; j++) {
                int id = tid + 256 * j;          // (n, kg) kg 0..15
                int n = id & 127, kg = id >> 7;
                const float* Wk = W + (long long)(kb * 64 + kg * 4) * 128 + n;
                float x0 = Wk[0], x1 = Wk[128], x2 = Wk[256], x3 = Wk[384];
                uint32_t h01, l01, h23, l23;
                split2_bf16(x0, x1, h01, l01);
                split2_bf16(x2, x3, h23, l23);
                *(uint2*)&Bsh[n * WP + kg * 2] = make_uint2(h01, h23);
                *(uint2*)&Bsl[n * WP + kg * 2] = make_uint2(l01, l23);
            }
        } else {
            // zero both planes then fill 2 heads of this K-block
#pragma unroll
            for (int j = 0; j < 9; j++) {
                int id = tid + 256 * j;          // 1152 uint4 per plane
                if (id < 1152) {
                    ((uint4*)Bsh)[id] = make_uint4(0, 0, 0, 0);
                    ((uint4*)Bsl)[id] = make_uint4(0, 0, 0, 0);
                }
            }
            __syncthreads();
            uint16_t* Bh16 = (uint16_t*)Bsh;
            uint16_t* Bl16 = (uint16_t*)Bsl;
#pragma unroll
            for (int j = 0; j < 8; j++) {
                int id = tid + 256 * j;          // 2048: h2, dk, dm
                int h2 = id >> 10, dk = (id >> 5) & 31, dm = id & 31;
                int h = kb * 2 + h2;
                float val = W[h * 1024 + dk * 32 + dm];
                uint32_t p = pack_bf16(val, 0.0f);
                float resid = val - __uint_as_float(p << 16);
                uint32_t pl = pack_bf16(resid, 0.0f);
                int n = h * 32 + dm, kloc = h2 * 32 + dk;
                Bh16[n * (WP * 2) + kloc] = (uint16_t)(p & 0xffff);
                Bl16[n * (WP * 2) + kloc] = (uint16_t)(pl & 0xffff);
            }
        }
        __syncthreads();

        // ---- compute: 4 k16-steps, 3xBF16 ----
#pragma unroll
        for (int ks = 0; ks < 4; ks++) {
            int ub = ks * 8 + t4;
            uint32_t ah[2][4], al[2][4];
#pragma unroll
            for (int mt = 0; mt < 2; mt++) {
                int rb = warpM * 32 + mt * 16 + g8;
                int base = rb * WP + ub;
                ah[mt][0] = Ash[base];
                ah[mt][1] = Ash[base + 8 * WP];
                ah[mt][2] = Ash[base + 4];
                ah[mt][3] = Ash[base + 8 * WP + 4];
                al[mt][0] = Asl[base];
                al[mt][1] = Asl[base + 8 * WP];
                al[mt][2] = Asl[base + 4];
                al[mt][3] = Asl[base + 8 * WP + 4];
            }
#pragma unroll
            for (int nt = 0; nt < 8; nt++) {
                int nb = warpN * 64 + nt * 8 + g8;
                int bbase = nb * WP + ub;
                uint32_t bh0 = Bsh[bbase], bh1 = Bsh[bbase + 4];
                uint32_t bl0 = Bsl[bbase], bl1 = Bsl[bbase + 4];
                mma_bf16(acc[0][nt], ah[0], bh0, bh1);
                mma_bf16(acc[1][nt], ah[1], bh0, bh1);
                mma_bf16(acc[0][nt], ah[0], bl0, bl1);
                mma_bf16(acc[1][nt], ah[1], bl0, bl1);
                mma_bf16(acc[0][nt], al[0], bh0, bh1);
                mma_bf16(acc[1][nt], al[1], bh0, bh1);
            }
        }
    }

    // ---- epilogue: acc -> Cs (staged) -> coalesced GMEM ----
    __syncthreads();
#pragma unroll
    for (int mt = 0; mt < 2; mt++) {
        int r0 = warpM * 32 + mt * 16 + g8;
#pragma unroll
        for (int nt = 0; nt < 8; nt++) {
            int cc = warpN * 64 + nt * 8 + 2 * t4;
            Cs[r0 * CP + cc]           = acc[mt][nt][0];
            Cs[r0 * CP + cc + 1]       = acc[mt][nt][1];
            Cs[(r0 + 8) * CP + cc]     = acc[mt][nt][2];
            Cs[(r0 + 8) * CP + cc + 1] = acc[mt][nt][3];
        }
    }
    __syncthreads();
#pragma unroll
    for (int j = 0; j < 16; j++) {
        int id = tid + 256 * j;                  // 4096 float4 slots
        int r = id >> 5, c4 = id & 31;
        int node = rowmap[r];
        if (node >= 0) {
            float4 v = *(const float4*)&Cs[r * CP + c4 * 4];
            if (bias) {
                v.x += bias[c4 * 4 + 0]; v.y += bias[c4 * 4 + 1];
                v.z += bias[c4 * 4 + 2]; v.w += bias[c4 * 4 + 3];
            }
            *(float4*)&C[(long long)node * 128 + c4 * 4] = v;
        }
    }
}

// ---------------- setup ----------------
__global__ void k_init() {
    int tid = blockIdx.x * 256 + threadIdx.x;
    if (tid < NH) { g_mx[tid] = __int_as_float(0xff800000); g_den[tid] = 0.0f; }
    if (tid < Nn) g_deg[tid] = 0;
    if (tid < Tt) { g_tcount[tid] = 0; g_cursor[tid] = 0; }
}
__global__ void k_count(const int* __restrict__ node_type, const int* __restrict__ ei) {
    int tid = blockIdx.x * 256 + threadIdx.x;
    if (tid < Nn) atomicAdd(&g_tcount[node_type[tid]], 1);
    if (tid < Ee) atomicAdd(&g_deg[ei[Ee + tid]], 1);
}
__global__ void k_scan() {
    if (threadIdx.x == 0 && blockIdx.x == 0) {
        g_toff[0] = 0;
        for (int t = 0; t < Tt; t++) g_toff[t + 1] = g_toff[t] + g_tcount[t];
    }
}
__global__ void k_scatter(const int* __restrict__ node_type) {
    int tid = blockIdx.x * 256 + threadIdx.x;
    if (tid < Nn) {
        int t = node_type[tid];
        int pos = g_toff[t] + atomicAdd(&g_cursor[t], 1);
        g_perm[pos] = tid;
    }
}

// ---------------- FFMA2 GEMM (tiny wcomb only) ------------------------------
#define GEMM_INNER(AS, BS)                                                   \
    _Pragma("unroll")                                                        \
    for (int k = 0; k < 32; k++) {                                           \
        const float4 av = *(const float4*)&AS;                               \
        ull a0 = dup2(av.x), a1 = dup2(av.y), a2 = dup2(av.z), a3 = dup2(av.w); \
        _Pragma("unroll")                                                    \
        for (int j4 = 0; j4 < 4; j4++) {                                     \
            const float4 bv = *(const float4*)&BS;                           \
            ull b0 = pack2(bv.x, bv.y), b1 = pack2(bv.z, bv.w);              \
            fma2(acc[0][2*j4], a0, b0); fma2(acc[0][2*j4+1], a0, b1);        \
            fma2(acc[1][2*j4], a1, b0); fma2(acc[1][2*j4+1], a1, b1);        \
            fma2(acc[2][2*j4], a2, b0); fma2(acc[2][2*j4+1], a2, b1);        \
            fma2(acc[3][2*j4], a3, b0); fma2(acc[3][2*j4+1], a3, b1);        \
        }                                                                    \
    }

__global__ void __launch_bounds__(256) k_gemm2(
    const float* __restrict__ Ab, long long sA,
    const float* __restrict__ Bb, long long sB,
    const float* __restrict__ biasb, long long sBias,
    float* __restrict__ Cb, long long sC, int M)
{
    const float* A = Ab + (long long)blockIdx.z * sA;
    const float* B = Bb + (long long)blockIdx.z * sB;
    const float* bias = biasb ? (biasb + (long long)blockIdx.z * sBias) : nullptr;
    float* C = Cb + (long long)blockIdx.z * sC;
    int row0 = blockIdx.x * 128;
    if (row0 >= M) return;

    __shared__ float Bs[32][132];
    __shared__ float AsT[32][132];
    int tid = threadIdx.x;
    int tr = tid >> 3, tc = tid & 7;

    ull acc[4][8];
#pragma unroll
    for (int i = 0; i < 4; i++)
#pragma unroll
        for (int j = 0; j < 8; j++) acc[i][j] = 0ULL;

#pragma unroll 1
    for (int kc = 0; kc < 4; kc++) {
        __syncthreads();
#pragma unroll
        for (int j = 0; j < 4; j++) {
            int id = tid + 256 * j;
            int brow = id >> 5, bc = id & 31;
            float4 v = *(const float4*)&B[(kc * 32 + brow) * 128 + bc * 4];
            *(float4*)&Bs[brow][(bc & 3) * 32 + (bc >> 2) * 4] = v;
        }
#pragma unroll
        for (int j = 0; j < 4; j++) {
            int id = tid + 256 * j;
            int arow = id >> 3, a4 = id & 7;
            int grow = row0 + arow;
            float4 v = make_float4(0.f, 0.f, 0.f, 0.f);
            if (grow < M) v = *(const float4*)&A[(long long)grow * 128 + kc * 32 + a4 * 4];
            AsT[a4 * 4 + 0][arow] = v.x;
            AsT[a4 * 4 + 1][arow] = v.y;
            AsT[a4 * 4 + 2][arow] = v.z;
            AsT[a4 * 4 + 3][arow] = v.w;
        }
        __syncthreads();
        GEMM_INNER(AsT[k][tr * 4], Bs[k][j4 * 32 + tc * 4])
    }

#pragma unroll
    for (int i = 0; i < 4; i++) {
        int grow = row0 + tr * 4 + i;
        if (grow < M) {
#pragma unroll
            for (int j4 = 0; j4 < 4; j4++) {
                float2 u0 = unpack2(acc[i][2 * j4]);
                float2 u1 = unpack2(acc[i][2 * j4 + 1]);
                int col = tc * 16 + j4 * 4;
                float4 o = make_float4(u0.x, u0.y, u1.x, u1.y);
                if (bias) {
                    o.x += bias[col]; o.y += bias[col + 1];
                    o.z += bias[col + 2]; o.w += bias[col + 3];
                }
                *(float4*)&C[(long long)grow * 128 + col] = o;
            }
        }
    }
}

// ---------------- edge logits + segment max (thread per edge-head) ----------
__global__ void __launch_bounds__(256) k_logits4(
    const int* __restrict__ ei, const int* __restrict__ et,
    const float* __restrict__ rel_pri)
{
    int tid = blockIdx.x * 256 + threadIdx.x;
    if (tid >= EH) return;
    int e = tid >> 2, h = tid & 3;
    int s = ei[e], t = ei[Ee + e], r = et[e];
    const float4* q = (const float4*)(g_qn + (long long)t * 128 + h * 32);
    const float4* kk = (const float4*)(g_knr + ((long long)r * Nn + s) * 128 + h * 32);
    float a0 = 0.f, a1 = 0.f;
#pragma unroll
    for (int i = 0; i < 8; i += 2) {
        float4 x = q[i], y = kk[i];
        a0 += x.x * y.x + x.y * y.y + x.z * y.z + x.w * y.w;
        float4 x1 = q[i + 1], y1 = kk[i + 1];
        a1 += x1.x * y1.x + x1.y * y1.y + x1.z * y1.z + x1.w * y1.w;
    }
    float lg = (a0 + a1) * rel_pri[r * 4 + h] * 0.17677669529663687f;
    g_ex[tid] = lg;
    atomicMaxF(&g_mx[t * 4 + h], lg);
}

// ---------------- exp + denominator (vectorized: one thread per edge) -------
__global__ void k_expden4(const int* __restrict__ ei) {
    int e = blockIdx.x * 256 + threadIdx.x;
    if (e >= Ee) return;
    int t = ei[Ee + e];
    float4 lg = *(const float4*)&g_ex[e * 4];
    float4 m = *(const float4*)&g_mx[t * 4];
    float4 v;
    v.x = expf(lg.x - m.x);
    v.y = expf(lg.y - m.y);
    v.z = expf(lg.z - m.z);
    v.w = expf(lg.w - m.w);
    *(float4*)&g_ex[e * 4] = v;
    atomicAdd(&g_den[t * 4 + 0], v.x);
    atomicAdd(&g_den[t * 4 + 1], v.y);
    atomicAdd(&g_den[t * 4 + 2], v.z);
    atomicAdd(&g_den[t * 4 + 3], v.w);
}

// ---------------- messages (only edge ids < N matter) -----------------------
__global__ void __launch_bounds__(256) k_msg(
    const int* __restrict__ ei, const int* __restrict__ et,
    const float* __restrict__ rel_msg)
{
    extern __shared__ float sh[];
    float* relS = sh;
    float* vnS = sh + RELF;
    for (int i = threadIdx.x; i < RELF; i += 256) relS[i] = rel_msg[i];
    __syncthreads();

    int warp = threadIdx.x >> 5, lane = threadIdx.x & 31;
    float* vW = vnS + warp * 128;
    int stride = gridDim.x * 8;
    for (int n = blockIdx.x * 8 + warp; n < Nn; n += stride) {
        int s = ei[n], t = ei[Ee + n], r = et[n];
        __syncwarp();
#pragma unroll
        for (int h = 0; h < 4; h++)
            vW[h * 32 + lane] = g_vn[(long long)s * 128 + h * 32 + lane];
        __syncwarp();
        float deg = (float)g_deg[n];
#pragma unroll
        for (int h = 0; h < 4; h++) {
            float att = g_ex[n * 4 + h] / (g_den[t * 4 + h] + 1e-16f);
            const float* Am = relS + (r * 4 + h) * 1024;
            float a0 = 0.f, a1 = 0.f;
#pragma unroll
            for (int d = 0; d < 32; d += 2) {
                a0 = fmaf(vW[h * 32 + d],     Am[d * 32 + lane],       a0);
                a1 = fmaf(vW[h * 32 + d + 1], Am[(d + 1) * 32 + lane], a1);
            }
            float vp = a0 + a1;
            float c = att * deg;
            long long o = (long long)n * 128 + h * 32 + lane;
            float m1 = vp * c;
            float m2 = vp * vp * c;
            float m3 = vp * vp * vp * c;
            float s3 = (m3 > 0.f) ? 1.f : ((m3 < 0.f) ? -1.f : 0.f);
            float r3 = s3 * powf(fabsf(m3) + 1e-18f, 0.33333333333333333f);
            g_agg[o] = m1;
            g_agg[ND + o] = m2;
            g_agg[2 * ND + o] = r3;
        }
    }
}

// ---------------- bfront[k] = bq @ Wak[k] -----------------------------------
__global__ void k_bfront(const float* __restrict__ Wak, const float* __restrict__ bq) {
    int kk = blockIdx.x, j = threadIdx.x;
    float s = 0.f;
#pragma unroll 4
    for (int d = 0; d < 128; d++)
        s = fmaf(bq[d], Wak[kk * 16384 + d * 128 + j], s);
    g_bfront[kk * 128 + j] = s;
}

// ---------------- gating + residual + gelu ----------------------------------
__global__ void __launch_bounds__(256) k_res() {
    int warp = threadIdx.x >> 5, lane = threadIdx.x & 31;
    int n = blockIdx.x * 8 + warp;
    if (n >= Nn) return;
    long long base = (long long)n * 128 + lane * 4;
    float r0 = 0.f, r1 = 0.f, r2 = 0.f, r3 = 0.f;
#pragma unroll
    for (int kk = 0; kk < 3; kk++) {
        const float4 f = *(const float4*)&g_front[kk * ND + base];
        const float4 t4 = *(const float4*)&g_tail[kk * ND + base];
        float p = f.x * t4.x + f.y * t4.y + f.z * t4.z + f.w * t4.w;
#pragma unroll
        for (int o = 16; o > 0; o >>= 1) p += __shfl_xor_sync(0xffffffffu, p, o);
        float tt = sigmoidf_(p);
        const float4 am = *(const float4*)&g_aggm[kk * ND + base];
        r0 = fmaf(tt, am.x, r0);
        r1 = fmaf(tt, am.y, r1);
        r2 = fmaf(tt, am.z, r2);
        r3 = fmaf(tt, am.w, r3);
    }
    float4 o;
    o.x = 0.5f * r0 * (1.0f + erff(r0 * 0.70710678118654752f));
    o.y = 0.5f * r1 * (1.0f + erff(r1 * 0.70710678118654752f));
    o.z = 0.5f * r2 * (1.0f + erff(r2 * 0.70710678118654752f));
    o.w = 0.5f * r3 * (1.0f + erff(r3 * 0.70710678118654752f));
    *(float4*)&g_hbuf[base] = o;
}

// ---------------- skip-mix + per-type LayerNorm -----------------------------
__global__ void __launch_bounds__(256) k_final(
    const float* __restrict__ meta, const int* __restrict__ node_type,
    const float* __restrict__ skip, const float* __restrict__ ln_g,
    const float* __restrict__ ln_b, float* __restrict__ out)
{
    int warp = threadIdx.x >> 5, lane = threadIdx.x & 31;
    int n = blockIdx.x * 8 + warp;
    if (n >= Nn) return;
    int t = node_type[n];
    float alpha = sigmoidf_(skip[t]);
    long long base = (long long)n * 128 + lane * 4;
    const float4 tr = *(const float4*)&g_trans[base];
    const float4 x = *(const float4*)&meta[base];
    float y0 = tr.x * alpha + x.x * (1.0f - alpha);
    float y1 = tr.y * alpha + x.y * (1.0f - alpha);
    float y2 = tr.z * alpha + x.z * (1.0f - alpha);
    float y3 = tr.w * alpha + x.w * (1.0f - alpha);
    float s = y0 + y1 + y2 + y3;
    float sq = y0 * y0 + y1 * y1 + y2 * y2 + y3 * y3;
#pragma unroll
    for (int o = 16; o > 0; o >>= 1) {
        s += __shfl_xor_sync(0xffffffffu, s, o);
        sq += __shfl_xor_sync(0xffffffffu, sq, o);
    }
    float mu = s * (1.0f / 128.0f);
    float var = sq * (1.0f / 128.0f) - mu * mu;
    float inv = 1.0f / sqrtf(var + 1e-5f);
    int c = lane * 4;
    const float4 g = *(const float4*)&ln_g[t * 128 + c];
    const float4 b = *(const float4*)&ln_b[t * 128 + c];
    float4 o;
    o.x = (y0 - mu) * inv * g.x + b.x;
    o.y = (y1 - mu) * inv * g.y + b.y;
    o.z = (y2 - mu) * inv * g.z + b.z;
    o.w = (y3 - mu) * inv * g.w + b.w;
    *(float4*)&out[base] = o;
}

// ---------------- host launcher ---------------------------------------------
extern "C" void kernel_launch(void* const* d_in, const int* in_sizes, int n_in,
                              void* d_out, int out_size)
{
    const float* meta      = (const float*)d_in[0];
    const int*   node_type = (const int*)d_in[1];
    const int*   ei        = (const int*)d_in[2];
    const int*   etype     = (const int*)d_in[3];
    const float* q_w = (const float*)d_in[5];
    const float* q_b = (const float*)d_in[6];
    const float* k_w = (const float*)d_in[7];
    const float* k_b = (const float*)d_in[8];
    const float* v_w = (const float*)d_in[9];
    const float* v_b = (const float*)d_in[10];
    const float* a_w = (const float*)d_in[11];
    const float* a_b = (const float*)d_in[12];
    const float* rel_pri = (const float*)d_in[13];
    const float* rel_att = (const float*)d_in[14];
    const float* rel_msg = (const float*)d_in[15];
    const float* WMk = (const float*)d_in[16];
    const float* Wak = (const float*)d_in[17];
    const float* Wq  = (const float*)d_in[18];
    const float* bq  = (const float*)d_in[19];
    const float* Wkl = (const float*)d_in[20];
    const float* bkl = (const float*)d_in[21];
    const float* skip = (const float*)d_in[22];
    const float* ln_g = (const float*)d_in[23];
    const float* ln_b = (const float*)d_in[24];
    float* out = (float*)d_out;

    float *p_qn, *p_kn, *p_vn, *p_knr, *p_agg, *p_aggm, *p_front, *p_tail,
          *p_hbuf, *p_trans, *p_wcomb, *p_bfront;
    cudaGetSymbolAddress((void**)&p_qn, g_qn);
    cudaGetSymbolAddress((void**)&p_kn, g_kn);
    cudaGetSymbolAddress((void**)&p_vn, g_vn);
    cudaGetSymbolAddress((void**)&p_knr, g_knr);
    cudaGetSymbolAddress((void**)&p_agg, g_agg);
    cudaGetSymbolAddress((void**)&p_aggm, g_aggm);
    cudaGetSymbolAddress((void**)&p_front, g_front);
    cudaGetSymbolAddress((void**)&p_tail, g_tail);
    cudaGetSymbolAddress((void**)&p_hbuf, g_hbuf);
    cudaGetSymbolAddress((void**)&p_trans, g_trans);
    cudaGetSymbolAddress((void**)&p_wcomb, g_wcomb);
    cudaGetSymbolAddress((void**)&p_bfront, g_bfront);

    const int SMEM_EDGE = (RELF + 8 * 128) * 4;               // 86016 B
    cudaFuncSetAttribute(k_msg, cudaFuncAttributeMaxDynamicSharedMemorySize, SMEM_EDGE);
    cudaFuncSetAttribute(k_mma, cudaFuncAttributeMaxDynamicSharedMemorySize, MM_TOT);

    dim3 blk(256);
    const int GB = 313;   // ceil(40000/128)

    k_init<<<625, blk>>>();
    k_count<<<1250, blk>>>(node_type, ei);
    k_scan<<<1, 32>>>();
    k_scatter<<<157, blk>>>(node_type);

    // typed q/k/v projections (bf16x3 mma.sync)
    k_mma<<<dim3(GB, 3), blk, MM_TOT>>>(meta, 0, q_w, 16384, q_b, 128, p_qn, 0, Nn, 1);
    k_mma<<<dim3(GB, 3), blk, MM_TOT>>>(meta, 0, k_w, 16384, k_b, 128, p_kn, 0, Nn, 1);
    k_mma<<<dim3(GB, 3), blk, MM_TOT>>>(meta, 0, v_w, 16384, v_b, 128, p_vn, 0, Nn, 1);

    // fold qlin: Wcomb[k] = Wq @ Wak[k]; bfront[k] = bq @ Wak[k]  (tiny, FFMA2)
    k_gemm2<<<dim3(1, 1, 3), blk>>>(Wq, 0, Wak, 16384, nullptr, 0, p_wcomb, 16384, 128);
    k_bfront<<<3, 128>>>(Wak, bq);

    // knr[r] = kn @ blockdiag(rel_att[r])   (bf16x3, mode 2)
    k_mma<<<dim3(GB, 5), blk, MM_TOT>>>(p_kn, 0, rel_att, 4096, nullptr, 0, p_knr, ND, Nn, 2);

    // logits + segment max; exp + denominators
    k_logits4<<<5000, blk>>>(ei, etype, rel_pri);
    k_expden4<<<1250, blk>>>(ei);

    // messages for edge ids < N (reference aggregate quirk: deg * msg[n])
    k_msg<<<296, blk, SMEM_EDGE>>>(ei, etype, rel_msg);

    // aggm[k] = agg[k] @ WMk[k]
    k_mma<<<dim3(GB, 3), blk, MM_TOT>>>(p_agg, ND, WMk, 16384, nullptr, 0, p_aggm, ND, Nn, 0);
    // front[k] = meta @ Wcomb[k] + bfront[k]
    k_mma<<<dim3(GB, 3), blk, MM_TOT>>>(meta, 0, p_wcomb, 16384, p_bfront, 128, p_front, ND, Nn, 0);
    // tail[k] = aggm[k] @ Wkl + bkl
    k_mma<<<dim3(GB, 3), blk, MM_TOT>>>(p_aggm, ND, Wkl, 0, bkl, 0, p_tail, ND, Nn, 0);

    k_res<<<5000, blk>>>();

    // trans = typed(gelu(res), a_w, a_b)
    k_mma<<<dim3(GB, 3), blk, MM_TOT>>>(p_hbuf, 0, a_w, 16384, a_b, 128, p_trans, 0, Nn, 1);

    k_final<<<5000, blk>>>(meta, node_type, skip, ln_g, ln_b, out);
}

// round 13
// speedup vs baseline: 1.6825x; 1.1006x over previous
#include <cuda_runtime.h>
#include <cuda_bf16.h>
#include <math.h>
#include <stdint.h>

#define Nn 40000
#define Ee 320000
#define Dd 128
#define Hh 4
#define DK 32
#define Tt 3
#define Rr 5
#define Kk 3
#define ND 5120000      // N*D
#define EH 1280000      // E*H
#define NH 160000       // N*H
#define RELF 20480      // R*H*DK*DK floats

typedef unsigned long long ull;

// ---------------- device scratch ----------------
__device__ __align__(16) float g_qn[ND];
__device__ __align__(16) float g_kn[ND];
__device__ __align__(16) float g_vn[ND];
__device__ __align__(16) float g_knr[Rr * ND];   // [r][n][128]
__device__ __align__(16) float g_ex[EH];
__device__ __align__(16) float g_mx[NH];
__device__ __align__(16) float g_den[NH];
__device__ int   g_deg[Nn];
__device__ int   g_perm[Nn];
__device__ int   g_tcount[Tt];
__device__ int   g_toff[Tt + 1];
__device__ int   g_cursor[Tt];
__device__ __align__(16) float g_agg[Kk * ND];
__device__ __align__(16) float g_aggm[Kk * ND];
__device__ __align__(16) float g_front[Kk * ND];
__device__ __align__(16) float g_tail[Kk * ND];
__device__ __align__(16) float g_hbuf[ND];
__device__ __align__(16) float g_trans[ND];
__device__ __align__(16) float g_wcomb[Kk * 16384];
__device__ __align__(16) float g_wmkl[Kk * 16384];
__device__ __align__(16) float g_bfront[Kk * 128];

// ---------------- small helpers ----------------
__device__ __forceinline__ float sigmoidf_(float x) { return 1.0f / (1.0f + expf(-x)); }

__device__ __forceinline__ void atomicMaxF(float* addr, float v) {
    int old = __float_as_int(*addr);
    while (__int_as_float(old) < v) {
        int prev = atomicCAS((int*)addr, old, __float_as_int(v));
        if (prev == old) break;
        old = prev;
    }
}

__device__ __forceinline__ void fma2(ull& d, ull a, ull b) {
    asm("fma.rn.f32x2 %0, %1, %2, %0;" : "+l"(d) : "l"(a), "l"(b));
}
__device__ __forceinline__ ull dup2(float x) {
    ull r; asm("mov.b64 %0, {%1, %1};" : "=l"(r) : "f"(x)); return r;
}
__device__ __forceinline__ ull pack2(float x, float y) {
    ull r; asm("mov.b64 %0, {%1, %2};" : "=l"(r) : "f"(x), "f"(y)); return r;
}
__device__ __forceinline__ float2 unpack2(ull v) {
    float2 f; asm("mov.b64 {%0, %1}, %2;" : "=f"(f.x), "=f"(f.y) : "l"(v)); return f;
}

// pack two floats to bf16x2 (low = x, high = y), round-to-nearest
__device__ __forceinline__ uint32_t pack_bf16(float x, float y) {
    uint32_t r; asm("cvt.rn.bf16x2.f32 %0, %1, %2;" : "=r"(r) : "f"(y), "f"(x));
    return r;
}
// split pair (x,y) into hi bf16x2 + lo bf16x2 (residual)
__device__ __forceinline__ void split2_bf16(float x, float y, uint32_t& hi, uint32_t& lo) {
    hi = pack_bf16(x, y);
    float rx = x - __uint_as_float(hi << 16);
    float ry = y - __uint_as_float(hi & 0xffff0000u);
    lo = pack_bf16(rx, ry);
}

// mma.sync m16n8k16 bf16 (baseline PTX)
__device__ __forceinline__ void mma_bf16(float* c, const uint32_t* a,
                                         uint32_t b0, uint32_t b1) {
    asm volatile(
        "mma.sync.aligned.m16n8k16.row.col.f32.bf16.bf16.f32 "
        "{%0,%1,%2,%3}, {%4,%5,%6,%7}, {%8,%9}, {%0,%1,%2,%3};"
        : "+f"(c[0]), "+f"(c[1]), "+f"(c[2]), "+f"(c[3])
        : "r"(a[0]), "r"(a[1]), "r"(a[2]), "r"(a[3]), "r"(b0), "r"(b1));
}

// SMEM layout (same as round 8/12 k_mma)
#define MM_ROWMAP 0
#define MM_ASH    512
#define MM_ASL    18944
#define MM_BSH    37376
#define MM_BSL    55808
#define MM_TOT    74240
#define WP 36
#define CP 132

// ---------------- GEMM core (shared by both kernels) -------------------------
// All-dense/typed body. Stages A rows (via rowmap) + B = W^T, bf16x3 compute.
struct Job {
    const float* A;
    const float* W;
    const float* bias;
    float* C;
    int typed;   // 1 => rows are g_perm[toff[type]..toff[type+1])
    int type;
};
struct Jobs9 { Job j[9]; };

__device__ __forceinline__ void mma_body(
    const float* __restrict__ A, const float* __restrict__ W,
    const float* __restrict__ bias, float* __restrict__ C,
    int row0, int rend, char* smem)
{
    int* rowmap = (int*)(smem + MM_ROWMAP);
    uint32_t* Ash = (uint32_t*)(smem + MM_ASH);
    uint32_t* Asl = (uint32_t*)(smem + MM_ASL);
    uint32_t* Bsh = (uint32_t*)(smem + MM_BSH);
    uint32_t* Bsl = (uint32_t*)(smem + MM_BSL);
    float* Cs = (float*)(smem + MM_ASH);

    int tid = threadIdx.x;
    int lane = tid & 31;
    int warp = tid >> 5;
    int warpM = warp >> 1, warpN = warp & 1;
    int g8 = lane >> 2, t4 = lane & 3;

    float acc[2][8][4];
#pragma unroll
    for (int mt = 0; mt < 2; mt++)
#pragma unroll
        for (int nt = 0; nt < 8; nt++)
#pragma unroll
            for (int c = 0; c < 4; c++) acc[mt][nt][c] = 0.0f;

#pragma unroll 1
    for (int kb = 0; kb < 2; kb++) {
        __syncthreads();
#pragma unroll
        for (int j = 0; j < 8; j++) {
            int id = tid + 256 * j;
            int r = id >> 4, k4 = id & 15;
            int node = rowmap[r];
            float4 v = make_float4(0.f, 0.f, 0.f, 0.f);
            if (node >= 0) v = *(const float4*)&A[(long long)node * 128 + kb * 64 + k4 * 4];
            uint32_t h01, l01, h23, l23;
            split2_bf16(v.x, v.y, h01, l01);
            split2_bf16(v.z, v.w, h23, l23);
            *(uint2*)&Ash[r * WP + k4 * 2] = make_uint2(h01, h23);
            *(uint2*)&Asl[r * WP + k4 * 2] = make_uint2(l01, l23);
        }
#pragma unroll
        for (int j = 0; j < 8; j++) {
            int id = tid + 256 * j;
            int n = id & 127, kg = id >> 7;
            const float* Wk = W + (long long)(kb * 64 + kg * 4) * 128 + n;
            float x0 = Wk[0], x1 = Wk[128], x2 = Wk[256], x3 = Wk[384];
            uint32_t h01, l01, h23, l23;
            split2_bf16(x0, x1, h01, l01);
            split2_bf16(x2, x3, h23, l23);
            *(uint2*)&Bsh[n * WP + kg * 2] = make_uint2(h01, h23);
            *(uint2*)&Bsl[n * WP + kg * 2] = make_uint2(l01, l23);
        }
        __syncthreads();

#pragma unroll
        for (int ks = 0; ks < 4; ks++) {
            int ub = ks * 8 + t4;
            uint32_t ah[2][4], al[2][4];
#pragma unroll
            for (int mt = 0; mt < 2; mt++) {
                int rb = warpM * 32 + mt * 16 + g8;
                int base = rb * WP + ub;
                ah[mt][0] = Ash[base];
                ah[mt][1] = Ash[base + 8 * WP];
                ah[mt][2] = Ash[base + 4];
                ah[mt][3] = Ash[base + 8 * WP + 4];
                al[mt][0] = Asl[base];
                al[mt][1] = Asl[base + 8 * WP];
                al[mt][2] = Asl[base + 4];
                al[mt][3] = Asl[base + 8 * WP + 4];
            }
#pragma unroll
            for (int nt = 0; nt < 8; nt++) {
                int nb = warpN * 64 + nt * 8 + g8;
                int bbase = nb * WP + ub;
                uint32_t bh0 = Bsh[bbase], bh1 = Bsh[bbase + 4];
                uint32_t bl0 = Bsl[bbase], bl1 = Bsl[bbase + 4];
                mma_bf16(acc[0][nt], ah[0], bh0, bh1);
                mma_bf16(acc[1][nt], ah[1], bh0, bh1);
                mma_bf16(acc[0][nt], ah[0], bl0, bl1);
                mma_bf16(acc[1][nt], ah[1], bl0, bl1);
                mma_bf16(acc[0][nt], al[0], bh0, bh1);
                mma_bf16(acc[1][nt], al[1], bh0, bh1);
            }
        }
    }

    __syncthreads();
#pragma unroll
    for (int mt = 0; mt < 2; mt++) {
        int r0 = warpM * 32 + mt * 16 + g8;
#pragma unroll
        for (int nt = 0; nt < 8; nt++) {
            int cc = warpN * 64 + nt * 8 + 2 * t4;
            Cs[r0 * CP + cc]           = acc[mt][nt][0];
            Cs[r0 * CP + cc + 1]       = acc[mt][nt][1];
            Cs[(r0 + 8) * CP + cc]     = acc[mt][nt][2];
            Cs[(r0 + 8) * CP + cc + 1] = acc[mt][nt][3];
        }
    }
    __syncthreads();
#pragma unroll
    for (int j = 0; j < 16; j++) {
        int id = tid + 256 * j;
        int r = id >> 5, c4 = id & 31;
        int node = rowmap[r];
        if (node >= 0) {
            float4 v = *(const float4*)&Cs[r * CP + c4 * 4];
            if (bias) {
                v.x += bias[c4 * 4 + 0]; v.y += bias[c4 * 4 + 1];
                v.z += bias[c4 * 4 + 2]; v.w += bias[c4 * 4 + 3];
            }
            *(float4*)&C[(long long)node * 128 + c4 * 4] = v;
        }
    }
}

// ---------------- multi-job GEMM launch (dense or typed jobs) ----------------
__global__ void __launch_bounds__(256) k_mma_multi(Jobs9 jobs)
{
    extern __shared__ char smem[];
    Job jb = jobs.j[blockIdx.y];
    int row0, rend;
    if (jb.typed) {
        row0 = g_toff[jb.type] + blockIdx.x * 128;
        rend = g_toff[jb.type + 1];
    } else {
        row0 = blockIdx.x * 128;
        rend = Nn;
    }
    if (row0 >= rend) return;

    int* rowmap = (int*)(smem + MM_ROWMAP);
    if (threadIdx.x < 128) {
        int gr = row0 + threadIdx.x;
        int node = -1;
        if (gr < rend) node = jb.typed ? g_perm[gr] : gr;
        rowmap[threadIdx.x] = node;
    }
    mma_body(jb.A, jb.W, jb.bias, jb.C, row0, rend, smem);
}

// ---------------- knr kernel (block-diag rel, mode-2 of old k_mma) ----------
__global__ void __launch_bounds__(256) k_mma_rel(
    const float* __restrict__ Ab, const float* __restrict__ Wb,
    float* __restrict__ Cb, long long sC)
{
    extern __shared__ char smem[];
    int* rowmap = (int*)(smem + MM_ROWMAP);
    uint32_t* Ash = (uint32_t*)(smem + MM_ASH);
    uint32_t* Asl = (uint32_t*)(smem + MM_ASL);
    uint32_t* Bsh = (uint32_t*)(smem + MM_BSH);
    uint32_t* Bsl = (uint32_t*)(smem + MM_BSL);
    float* Cs = (float*)(smem + MM_ASH);

    int tid = threadIdx.x;
    int lane = tid & 31;
    int warp = tid >> 5;
    int warpM = warp >> 1, warpN = warp & 1;
    int g8 = lane >> 2, t4 = lane & 3;
    int z = blockIdx.y;

    const float* A = Ab;
    const float* W = Wb + (long long)z * 4096;
    float* C = Cb + (long long)z * sC;
    int row0 = blockIdx.x * 128;
    if (row0 >= Nn) return;

    if (tid < 128) {
        int gr = row0 + tid;
        rowmap[tid] = (gr < Nn) ? gr : -1;
    }

    float acc[2][8][4];
#pragma unroll
    for (int mt = 0; mt < 2; mt++)
#pragma unroll
        for (int nt = 0; nt < 8; nt++)
#pragma unroll
            for (int c = 0; c < 4; c++) acc[mt][nt][c] = 0.0f;

#pragma unroll 1
    for (int kb = 0; kb < 2; kb++) {
        __syncthreads();
#pragma unroll
        for (int j = 0; j < 8; j++) {
            int id = tid + 256 * j;
            int r = id >> 4, k4 = id & 15;
            int node = rowmap[r];
            float4 v = make_float4(0.f, 0.f, 0.f, 0.f);
            if (node >= 0) v = *(const float4*)&A[(long long)node * 128 + kb * 64 + k4 * 4];
            uint32_t h01, l01, h23, l23;
            split2_bf16(v.x, v.y, h01, l01);
            split2_bf16(v.z, v.w, h23, l23);
            *(uint2*)&Ash[r * WP + k4 * 2] = make_uint2(h01, h23);
            *(uint2*)&Asl[r * WP + k4 * 2] = make_uint2(l01, l23);
        }
        // zero then fill 2 heads of this K-block
#pragma unroll
        for (int j = 0; j < 9; j++) {
            int id = tid + 256 * j;
            if (id < 1152) {
                ((uint4*)Bsh)[id] = make_uint4(0, 0, 0, 0);
                ((uint4*)Bsl)[id] = make_uint4(0, 0, 0, 0);
            }
        }
        __syncthreads();
        uint16_t* Bh16 = (uint16_t*)Bsh;
        uint16_t* Bl16 = (uint16_t*)Bsl;
#pragma unroll
        for (int j = 0; j < 8; j++) {
            int id = tid + 256 * j;
            int h2 = id >> 10, dk = (id >> 5) & 31, dm = id & 31;
            int h = kb * 2 + h2;
            float val = W[h * 1024 + dk * 32 + dm];
            uint32_t p = pack_bf16(val, 0.0f);
            float resid = val - __uint_as_float(p << 16);
            uint32_t pl = pack_bf16(resid, 0.0f);
            int n = h * 32 + dm, kloc = h2 * 32 + dk;
            Bh16[n * (WP * 2) + kloc] = (uint16_t)(p & 0xffff);
            Bl16[n * (WP * 2) + kloc] = (uint16_t)(pl & 0xffff);
        }
        __syncthreads();

#pragma unroll
        for (int ks = 0; ks < 4; ks++) {
            int ub = ks * 8 + t4;
            uint32_t ah[2][4], al[2][4];
#pragma unroll
            for (int mt = 0; mt < 2; mt++) {
                int rb = warpM * 32 + mt * 16 + g8;
                int base = rb * WP + ub;
                ah[mt][0] = Ash[base];
                ah[mt][1] = Ash[base + 8 * WP];
                ah[mt][2] = Ash[base + 4];
                ah[mt][3] = Ash[base + 8 * WP + 4];
                al[mt][0] = Asl[base];
                al[mt][1] = Asl[base + 8 * WP];
                al[mt][2] = Asl[base + 4];
                al[mt][3] = Asl[base + 8 * WP + 4];
            }
#pragma unroll
            for (int nt = 0; nt < 8; nt++) {
                int nb = warpN * 64 + nt * 8 + g8;
                int bbase = nb * WP + ub;
                uint32_t bh0 = Bsh[bbase], bh1 = Bsh[bbase + 4];
                uint32_t bl0 = Bsl[bbase], bl1 = Bsl[bbase + 4];
                mma_bf16(acc[0][nt], ah[0], bh0, bh1);
                mma_bf16(acc[1][nt], ah[1], bh0, bh1);
                mma_bf16(acc[0][nt], ah[0], bl0, bl1);
                mma_bf16(acc[1][nt], ah[1], bl0, bl1);
                mma_bf16(acc[0][nt], al[0], bh0, bh1);
                mma_bf16(acc[1][nt], al[1], bh0, bh1);
            }
        }
    }

    __syncthreads();
#pragma unroll
    for (int mt = 0; mt < 2; mt++) {
        int r0 = warpM * 32 + mt * 16 + g8;
#pragma unroll
        for (int nt = 0; nt < 8; nt++) {
            int cc = warpN * 64 + nt * 8 + 2 * t4;
            Cs[r0 * CP + cc]           = acc[mt][nt][0];
            Cs[r0 * CP + cc + 1]       = acc[mt][nt][1];
            Cs[(r0 + 8) * CP + cc]     = acc[mt][nt][2];
            Cs[(r0 + 8) * CP + cc + 1] = acc[mt][nt][3];
        }
    }
    __syncthreads();
#pragma unroll
    for (int j = 0; j < 16; j++) {
        int id = tid + 256 * j;
        int r = id >> 5, c4 = id & 31;
        int node = rowmap[r];
        if (node >= 0) {
            float4 v = *(const float4*)&Cs[r * CP + c4 * 4];
            *(float4*)&C[(long long)node * 128 + c4 * 4] = v;
        }
    }
}

// ---------------- setup ----------------
__global__ void k_init() {
    int tid = blockIdx.x * 256 + threadIdx.x;
    if (tid < NH) { g_mx[tid] = __int_as_float(0xff800000); g_den[tid] = 0.0f; }
    if (tid < Nn) g_deg[tid] = 0;
    if (tid < Tt) { g_tcount[tid] = 0; g_cursor[tid] = 0; }
}
__global__ void k_count(const int* __restrict__ node_type, const int* __restrict__ ei) {
    int tid = blockIdx.x * 256 + threadIdx.x;
    if (tid < Nn) atomicAdd(&g_tcount[node_type[tid]], 1);
    if (tid < Ee) atomicAdd(&g_deg[ei[Ee + tid]], 1);
}
__global__ void k_scan() {
    if (threadIdx.x == 0 && blockIdx.x == 0) {
        g_toff[0] = 0;
        for (int t = 0; t < Tt; t++) g_toff[t + 1] = g_toff[t] + g_tcount[t];
    }
}
// block-aggregated scatter: 1 global atomic per (block, type)
__global__ void k_scatter(const int* __restrict__ node_type) {
    __shared__ int cnt[Tt], base[Tt];
    if (threadIdx.x < Tt) cnt[threadIdx.x] = 0;
    __syncthreads();
    int n = blockIdx.x * 256 + threadIdx.x;
    int t = -1, lp = 0;
    if (n < Nn) {
        t = node_type[n];
        lp = atomicAdd(&cnt[t], 1);
    }
    __syncthreads();
    if (threadIdx.x < Tt)
        base[threadIdx.x] = atomicAdd(&g_cursor[threadIdx.x], cnt[threadIdx.x]);
    __syncthreads();
    if (n < Nn)
        g_perm[g_toff[t] + base[t] + lp] = n;
}

// ---------------- FFMA2 GEMM (tiny weight-product GEMMs) --------------------
#define GEMM_INNER(AS, BS)                                                   \
    _Pragma("unroll")                                                        \
    for (int k = 0; k < 32; k++) {                                           \
        const float4 av = *(const float4*)&AS;                               \
        ull a0 = dup2(av.x), a1 = dup2(av.y), a2 = dup2(av.z), a3 = dup2(av.w); \
        _Pragma("unroll")                                                    \
        for (int j4 = 0; j4 < 4; j4++) {                                     \
            const float4 bv = *(const float4*)&BS;                           \
            ull b0 = pack2(bv.x, bv.y), b1 = pack2(bv.z, bv.w);              \
            fma2(acc[0][2*j4], a0, b0); fma2(acc[0][2*j4+1], a0, b1);        \
            fma2(acc[1][2*j4], a1, b0); fma2(acc[1][2*j4+1], a1, b1);        \
            fma2(acc[2][2*j4], a2, b0); fma2(acc[2][2*j4+1], a2, b1);        \
            fma2(acc[3][2*j4], a3, b0); fma2(acc[3][2*j4+1], a3, b1);        \
        }                                                                    \
    }

__global__ void __launch_bounds__(256) k_gemm2(
    const float* __restrict__ Ab, long long sA,
    const float* __restrict__ Bb, long long sB,
    const float* __restrict__ biasb, long long sBias,
    float* __restrict__ Cb, long long sC, int M)
{
    const float* A = Ab + (long long)blockIdx.z * sA;
    const float* B = Bb + (long long)blockIdx.z * sB;
    const float* bias = biasb ? (biasb + (long long)blockIdx.z * sBias) : nullptr;
    float* C = Cb + (long long)blockIdx.z * sC;
    int row0 = blockIdx.x * 128;
    if (row0 >= M) return;

    __shared__ float Bs[32][132];
    __shared__ float AsT[32][132];
    int tid = threadIdx.x;
    int tr = tid >> 3, tc = tid & 7;

    ull acc[4][8];
#pragma unroll
    for (int i = 0; i < 4; i++)
#pragma unroll
        for (int j = 0; j < 8; j++) acc[i][j] = 0ULL;

#pragma unroll 1
    for (int kc = 0; kc < 4; kc++) {
        __syncthreads();
#pragma unroll
        for (int j = 0; j < 4; j++) {
            int id = tid + 256 * j;
            int brow = id >> 5, bc = id & 31;
            float4 v = *(const float4*)&B[(kc * 32 + brow) * 128 + bc * 4];
            *(float4*)&Bs[brow][(bc & 3) * 32 + (bc >> 2) * 4] = v;
        }
#pragma unroll
        for (int j = 0; j < 4; j++) {
            int id = tid + 256 * j;
            int arow = id >> 3, a4 = id & 7;
            int grow = row0 + arow;
            float4 v = make_float4(0.f, 0.f, 0.f, 0.f);
            if (grow < M) v = *(const float4*)&A[(long long)grow * 128 + kc * 32 + a4 * 4];
            AsT[a4 * 4 + 0][arow] = v.x;
            AsT[a4 * 4 + 1][arow] = v.y;
            AsT[a4 * 4 + 2][arow] = v.z;
            AsT[a4 * 4 + 3][arow] = v.w;
        }
        __syncthreads();
        GEMM_INNER(AsT[k][tr * 4], Bs[k][j4 * 32 + tc * 4])
    }

#pragma unroll
    for (int i = 0; i < 4; i++) {
        int grow = row0 + tr * 4 + i;
        if (grow < M) {
#pragma unroll
            for (int j4 = 0; j4 < 4; j4++) {
                float2 u0 = unpack2(acc[i][2 * j4]);
                float2 u1 = unpack2(acc[i][2 * j4 + 1]);
                int col = tc * 16 + j4 * 4;
                float4 o = make_float4(u0.x, u0.y, u1.x, u1.y);
                if (bias) {
                    o.x += bias[col]; o.y += bias[col + 1];
                    o.z += bias[col + 2]; o.w += bias[col + 3];
                }
                *(float4*)&C[(long long)grow * 128 + col] = o;
            }
        }
    }
}

// ---------------- edge logits + segment max (thread per edge-head) ----------
__global__ void __launch_bounds__(256) k_logits4(
    const int* __restrict__ ei, const int* __restrict__ et,
    const float* __restrict__ rel_pri)
{
    int tid = blockIdx.x * 256 + threadIdx.x;
    if (tid >= EH) return;
    int e = tid >> 2, h = tid & 3;
    int s = ei[e], t = ei[Ee + e], r = et[e];
    const float4* q = (const float4*)(g_qn + (long long)t * 128 + h * 32);
    const float4* kk = (const float4*)(g_knr + ((long long)r * Nn + s) * 128 + h * 32);
    float a0 = 0.f, a1 = 0.f;
#pragma unroll
    for (int i = 0; i < 8; i += 2) {
        float4 x = q[i], y = kk[i];
        a0 += x.x * y.x + x.y * y.y + x.z * y.z + x.w * y.w;
        float4 x1 = q[i + 1], y1 = kk[i + 1];
        a1 += x1.x * y1.x + x1.y * y1.y + x1.z * y1.z + x1.w * y1.w;
    }
    float lg = (a0 + a1) * rel_pri[r * 4 + h] * 0.17677669529663687f;
    g_ex[tid] = lg;
    atomicMaxF(&g_mx[t * 4 + h], lg);
}

// ---------------- exp + denominator (one thread per edge) -------------------
__global__ void k_expden4(const int* __restrict__ ei) {
    int e = blockIdx.x * 256 + threadIdx.x;
    if (e >= Ee) return;
    int t = ei[Ee + e];
    float4 lg = *(const float4*)&g_ex[e * 4];
    float4 m = *(const float4*)&g_mx[t * 4];
    float4 v;
    v.x = expf(lg.x - m.x);
    v.y = expf(lg.y - m.y);
    v.z = expf(lg.z - m.z);
    v.w = expf(lg.w - m.w);
    *(float4*)&g_ex[e * 4] = v;
    atomicAdd(&g_den[t * 4 + 0], v.x);
    atomicAdd(&g_den[t * 4 + 1], v.y);
    atomicAdd(&g_den[t * 4 + 2], v.z);
    atomicAdd(&g_den[t * 4 + 3], v.w);
}

// ---------------- messages (only edge ids < N matter) -----------------------
__global__ void __launch_bounds__(256) k_msg(
    const int* __restrict__ ei, const int* __restrict__ et,
    const float* __restrict__ rel_msg)
{
    extern __shared__ float sh[];
    float* relS = sh;
    float* vnS = sh + RELF;
    for (int i = threadIdx.x; i < RELF; i += 256) relS[i] = rel_msg[i];
    __syncthreads();

    int warp = threadIdx.x >> 5, lane = threadIdx.x & 31;
    float* vW = vnS + warp * 128;
    int stride = gridDim.x * 8;
    for (int n = blockIdx.x * 8 + warp; n < Nn; n += stride) {
        int s = ei[n], t = ei[Ee + n], r = et[n];
        __syncwarp();
#pragma unroll
        for (int h = 0; h < 4; h++)
            vW[h * 32 + lane] = g_vn[(long long)s * 128 + h * 32 + lane];
        __syncwarp();
        float deg = (float)g_deg[n];
#pragma unroll
        for (int h = 0; h < 4; h++) {
            float att = g_ex[n * 4 + h] / (g_den[t * 4 + h] + 1e-16f);
            const float* Am = relS + (r * 4 + h) * 1024;
            float a0 = 0.f, a1 = 0.f;
#pragma unroll
            for (int d = 0; d < 32; d += 2) {
                a0 = fmaf(vW[h * 32 + d],     Am[d * 32 + lane],       a0);
                a1 = fmaf(vW[h * 32 + d + 1], Am[(d + 1) * 32 + lane], a1);
            }
            float vp = a0 + a1;
            float c = att * deg;
            long long o = (long long)n * 128 + h * 32 + lane;
            float m1 = vp * c;
            float m2 = vp * vp * c;
            float m3 = vp * vp * vp * c;
            float s3 = (m3 > 0.f) ? 1.f : ((m3 < 0.f) ? -1.f : 0.f);
            float r3 = s3 * powf(fabsf(m3) + 1e-18f, 0.33333333333333333f);
            g_agg[o] = m1;
            g_agg[ND + o] = m2;
            g_agg[2 * ND + o] = r3;
        }
    }
}

// ---------------- bfront[k] = bq @ Wak[k] -----------------------------------
__global__ void k_bfront(const float* __restrict__ Wak, const float* __restrict__ bq) {
    int kk = blockIdx.x, j = threadIdx.x;
    float s = 0.f;
#pragma unroll 4
    for (int d = 0; d < 128; d++)
        s = fmaf(bq[d], Wak[kk * 16384 + d * 128 + j], s);
    g_bfront[kk * 128 + j] = s;
}

// ---------------- gating + residual + gelu ----------------------------------
__global__ void __launch_bounds__(256) k_res() {
    int warp = threadIdx.x >> 5, lane = threadIdx.x & 31;
    int n = blockIdx.x * 8 + warp;
    if (n >= Nn) return;
    long long base = (long long)n * 128 + lane * 4;
    float r0 = 0.f, r1 = 0.f, r2 = 0.f, r3 = 0.f;
#pragma unroll
    for (int kk = 0; kk < 3; kk++) {
        const float4 f = *(const float4*)&g_front[kk * ND + base];
        const float4 t4 = *(const float4*)&g_tail[kk * ND + base];
        float p = f.x * t4.x + f.y * t4.y + f.z * t4.z + f.w * t4.w;
#pragma unroll
        for (int o = 16; o > 0; o >>= 1) p += __shfl_xor_sync(0xffffffffu, p, o);
        float tt = sigmoidf_(p);
        const float4 am = *(const float4*)&g_aggm[kk * ND + base];
        r0 = fmaf(tt, am.x, r0);
        r1 = fmaf(tt, am.y, r1);
        r2 = fmaf(tt, am.z, r2);
        r3 = fmaf(tt, am.w, r3);
    }
    float4 o;
    o.x = 0.5f * r0 * (1.0f + erff(r0 * 0.70710678118654752f));
    o.y = 0.5f * r1 * (1.0f + erff(r1 * 0.70710678118654752f));
    o.z = 0.5f * r2 * (1.0f + erff(r2 * 0.70710678118654752f));
    o.w = 0.5f * r3 * (1.0f + erff(r3 * 0.70710678118654752f));
    *(float4*)&g_hbuf[base] = o;
}

// ---------------- skip-mix + per-type LayerNorm -----------------------------
__global__ void __launch_bounds__(256) k_final(
    const float* __restrict__ meta, const int* __restrict__ node_type,
    const float* __restrict__ skip, const float* __restrict__ ln_g,
    const float* __restrict__ ln_b, float* __restrict__ out)
{
    int warp = threadIdx.x >> 5, lane = threadIdx.x & 31;
    int n = blockIdx.x * 8 + warp;
    if (n >= Nn) return;
    int t = node_type[n];
    float alpha = sigmoidf_(skip[t]);
    long long base = (long long)n * 128 + lane * 4;
    const float4 tr = *(const float4*)&g_trans[base];
    const float4 x = *(const float4*)&meta[base];
    float y0 = tr.x * alpha + x.x * (1.0f - alpha);
    float y1 = tr.y * alpha + x.y * (1.0f - alpha);
    float y2 = tr.z * alpha + x.z * (1.0f - alpha);
    float y3 = tr.w * alpha + x.w * (1.0f - alpha);
    float s = y0 + y1 + y2 + y3;
    float sq = y0 * y0 + y1 * y1 + y2 * y2 + y3 * y3;
#pragma unroll
    for (int o = 16; o > 0; o >>= 1) {
        s += __shfl_xor_sync(0xffffffffu, s, o);
        sq += __shfl_xor_sync(0xffffffffu, sq, o);
    }
    float mu = s * (1.0f / 128.0f);
    float var = sq * (1.0f / 128.0f) - mu * mu;
    float inv = 1.0f / sqrtf(var + 1e-5f);
    int c = lane * 4;
    const float4 g = *(const float4*)&ln_g[t * 128 + c];
    const float4 b = *(const float4*)&ln_b[t * 128 + c];
    float4 o;
    o.x = (y0 - mu) * inv * g.x + b.x;
    o.y = (y1 - mu) * inv * g.y + b.y;
    o.z = (y2 - mu) * inv * g.z + b.z;
    o.w = (y3 - mu) * inv * g.w + b.w;
    *(float4*)&out[base] = o;
}

// ---------------- host launcher ---------------------------------------------
extern "C" void kernel_launch(void* const* d_in, const int* in_sizes, int n_in,
                              void* d_out, int out_size)
{
    const float* meta      = (const float*)d_in[0];
    const int*   node_type = (const int*)d_in[1];
    const int*   ei        = (const int*)d_in[2];
    const int*   etype     = (const int*)d_in[3];
    const float* q_w = (const float*)d_in[5];
    const float* q_b = (const float*)d_in[6];
    const float* k_w = (const float*)d_in[7];
    const float* k_b = (const float*)d_in[8];
    const float* v_w = (const float*)d_in[9];
    const float* v_b = (const float*)d_in[10];
    const float* a_w = (const float*)d_in[11];
    const float* a_b = (const float*)d_in[12];
    const float* rel_pri = (const float*)d_in[13];
    const float* rel_att = (const float*)d_in[14];
    const float* rel_msg = (const float*)d_in[15];
    const float* WMk = (const float*)d_in[16];
    const float* Wak = (const float*)d_in[17];
    const float* Wq  = (const float*)d_in[18];
    const float* bq  = (const float*)d_in[19];
    const float* Wkl = (const float*)d_in[20];
    const float* bkl = (const float*)d_in[21];
    const float* skip = (const float*)d_in[22];
    const float* ln_g = (const float*)d_in[23];
    const float* ln_b = (const float*)d_in[24];
    float* out = (float*)d_out;

    float *p_qn, *p_kn, *p_vn, *p_knr, *p_agg, *p_aggm, *p_front, *p_tail,
          *p_hbuf, *p_trans, *p_wcomb, *p_wmkl, *p_bfront;
    cudaGetSymbolAddress((void**)&p_qn, g_qn);
    cudaGetSymbolAddress((void**)&p_kn, g_kn);
    cudaGetSymbolAddress((void**)&p_vn, g_vn);
    cudaGetSymbolAddress((void**)&p_knr, g_knr);
    cudaGetSymbolAddress((void**)&p_agg, g_agg);
    cudaGetSymbolAddress((void**)&p_aggm, g_aggm);
    cudaGetSymbolAddress((void**)&p_front, g_front);
    cudaGetSymbolAddress((void**)&p_tail, g_tail);
    cudaGetSymbolAddress((void**)&p_hbuf, g_hbuf);
    cudaGetSymbolAddress((void**)&p_trans, g_trans);
    cudaGetSymbolAddress((void**)&p_wcomb, g_wcomb);
    cudaGetSymbolAddress((void**)&p_wmkl, g_wmkl);
    cudaGetSymbolAddress((void**)&p_bfront, g_bfront);

    const int SMEM_EDGE = (RELF + 8 * 128) * 4;               // 86016 B
    cudaFuncSetAttribute(k_msg, cudaFuncAttributeMaxDynamicSharedMemorySize, SMEM_EDGE);
    cudaFuncSetAttribute(k_mma_multi, cudaFuncAttributeMaxDynamicSharedMemorySize, MM_TOT);
    cudaFuncSetAttribute(k_mma_rel, cudaFuncAttributeMaxDynamicSharedMemorySize, MM_TOT);

    dim3 blk(256);
    const int GB = 313;   // ceil(40000/128)

    k_init<<<625, blk>>>();
    k_count<<<1250, blk>>>(node_type, ei);
    k_scan<<<1, 32>>>();
    k_scatter<<<157, blk>>>(node_type);

    // tiny weight products (independent of everything above)
    k_gemm2<<<dim3(1, 1, 3), blk>>>(Wq, 0, Wak, 16384, nullptr, 0, p_wcomb, 16384, 128);
    k_gemm2<<<dim3(1, 1, 3), blk>>>(WMk, 16384, Wkl, 0, nullptr, 0, p_wmkl, 16384, 128);
    k_bfront<<<3, 128>>>(Wak, bq);

    // merged q/k/v typed projections: 9 jobs (matrix x type)
    {
        Jobs9 J;
        const float* Ws[3] = {q_w, k_w, v_w};
        const float* Bs_[3] = {q_b, k_b, v_b};
        float* Cs_[3] = {p_qn, p_kn, p_vn};
        for (int m = 0; m < 3; m++)
            for (int t = 0; t < 3; t++) {
                J.j[m * 3 + t] = Job{meta, Ws[m] + (long long)t * 16384,
                                     Bs_[m] + (long long)t * 128, Cs_[m], 1, t};
            }
        k_mma_multi<<<dim3(GB, 9), blk, MM_TOT>>>(J);
    }

    // knr[r] = kn @ blockdiag(rel_att[r])
    k_mma_rel<<<dim3(GB, 5), blk, MM_TOT>>>(p_kn, rel_att, p_knr, ND);

    // logits + segment max; exp + denominators
    k_logits4<<<5000, blk>>>(ei, etype, rel_pri);
    k_expden4<<<1250, blk>>>(ei);

    // messages for edge ids < N (reference aggregate quirk: deg * msg[n])
    k_msg<<<296, blk, SMEM_EDGE>>>(ei, etype, rel_msg);

    // merged aggm / tail / front: 9 dense jobs
    // aggm[k] = agg[k] @ WMk[k]
    // tail[k] = agg[k] @ WMkl[k] + bkl          (== aggm[k] @ Wkl + bkl)
    // front[k] = meta @ wcomb[k] + bfront[k]
    {
        Jobs9 J;
        for (int kk = 0; kk < 3; kk++) {
            J.j[kk]     = Job{p_agg + (long long)kk * ND, WMk + (long long)kk * 16384,
                              nullptr, p_aggm + (long long)kk * ND, 0, 0};
            J.j[3 + kk] = Job{p_agg + (long long)kk * ND, p_wmkl + (long long)kk * 16384,
                              bkl, p_tail + (long long)kk * ND, 0, 0};
            J.j[6 + kk] = Job{meta, p_wcomb + (long long)kk * 16384,
                              p_bfront + (long long)kk * 128, p_front + (long long)kk * ND, 0, 0};
        }
        k_mma_multi<<<dim3(GB, 9), blk, MM_TOT>>>(J);
    }

    k_res<<<5000, blk>>>();

    // trans = typed(gelu(res), a_w, a_b): 3 typed jobs
    {
        Jobs9 J;
        for (int t = 0; t < 3; t++)
            J.j[t] = Job{p_hbuf, a_w + (long long)t * 16384,
                         a_b + (long long)t * 128, p_trans, 1, t};
        for (int z = 3; z < 9; z++) J.j[z] = J.j[0];
        k_mma_multi<<<dim3(GB, 3), blk, MM_TOT>>>(J);
    }

    k_final<<<5000, blk>>>(meta, node_type, skip, ln_g, ln_b, out);
}

// round 14
// speedup vs baseline: 1.8274x; 1.0861x over previous
#include <cuda_runtime.h>
#include <cuda_bf16.h>
#include <math.h>
#include <stdint.h>

#define Nn 40000
#define Ee 320000
#define Dd 128
#define Hh 4
#define DK 32
#define Tt 3
#define Rr 5
#define Kk 3
#define ND 5120000      // N*D
#define EH 1280000      // E*H
#define NH 160000       // N*H
#define RELF 20480      // R*H*DK*DK floats

typedef unsigned long long ull;

// ---------------- device scratch ----------------
__device__ __align__(16) float g_qn[ND];
__device__ __align__(16) float g_kn[ND];
__device__ __align__(16) float g_vn[ND];
__device__ __align__(16) float g_knr[Rr * ND];   // [r][n][128]
__device__ __align__(16) float g_ex[EH];
__device__ __align__(16) float g_mx[NH];
__device__ __align__(16) float g_den[NH];
__device__ int   g_deg[Nn];
__device__ int   g_perm[Nn];
__device__ int   g_tcount[Tt];
__device__ int   g_toff[Tt + 1];
__device__ int   g_cursor[Tt];
__device__ __align__(16) float g_agg[Kk * ND];
__device__ __align__(16) float g_aggm[Kk * ND];
__device__ __align__(16) float g_u[Kk * ND];      // u[k] = agg[k] @ GT[k]^T + b2[k]
__device__ __align__(16) float g_hbuf[ND];
__device__ __align__(16) float g_trans[ND];
__device__ __align__(16) float g_wcomb[Kk * 16384];
__device__ __align__(16) float g_wcombT[Kk * 16384];
__device__ __align__(16) float g_wmkl[Kk * 16384];
__device__ __align__(16) float g_GT[Kk * 16384];
__device__ __align__(16) float g_bfront[Kk * 128];
__device__ __align__(16) float g_b2[Kk * 128];
__device__ __align__(16) float g_c3[Kk * 128];
__device__ float g_sD[Kk];

// ---------------- small helpers ----------------
__device__ __forceinline__ float sigmoidf_(float x) { return 1.0f / (1.0f + expf(-x)); }

__device__ __forceinline__ void atomicMaxF(float* addr, float v) {
    int old = __float_as_int(*addr);
    while (__int_as_float(old) < v) {
        int prev = atomicCAS((int*)addr, old, __float_as_int(v));
        if (prev == old) break;
        old = prev;
    }
}

__device__ __forceinline__ void fma2(ull& d, ull a, ull b) {
    asm("fma.rn.f32x2 %0, %1, %2, %0;" : "+l"(d) : "l"(a), "l"(b));
}
__device__ __forceinline__ ull dup2(float x) {
    ull r; asm("mov.b64 %0, {%1, %1};" : "=l"(r) : "f"(x)); return r;
}
__device__ __forceinline__ ull pack2(float x, float y) {
    ull r; asm("mov.b64 %0, {%1, %2};" : "=l"(r) : "f"(x), "f"(y)); return r;
}
__device__ __forceinline__ float2 unpack2(ull v) {
    float2 f; asm("mov.b64 {%0, %1}, %2;" : "=f"(f.x), "=f"(f.y) : "l"(v)); return f;
}

__device__ __forceinline__ uint32_t pack_bf16(float x, float y) {
    uint32_t r; asm("cvt.rn.bf16x2.f32 %0, %1, %2;" : "=r"(r) : "f"(y), "f"(x));
    return r;
}
__device__ __forceinline__ void split2_bf16(float x, float y, uint32_t& hi, uint32_t& lo) {
    hi = pack_bf16(x, y);
    float rx = x - __uint_as_float(hi << 16);
    float ry = y - __uint_as_float(hi & 0xffff0000u);
    lo = pack_bf16(rx, ry);
}

__device__ __forceinline__ void mma_bf16(float* c, const uint32_t* a,
                                         uint32_t b0, uint32_t b1) {
    asm volatile(
        "mma.sync.aligned.m16n8k16.row.col.f32.bf16.bf16.f32 "
        "{%0,%1,%2,%3}, {%4,%5,%6,%7}, {%8,%9}, {%0,%1,%2,%3};"
        : "+f"(c[0]), "+f"(c[1]), "+f"(c[2]), "+f"(c[3])
        : "r"(a[0]), "r"(a[1]), "r"(a[2]), "r"(a[3]), "r"(b0), "r"(b1));
}

// SMEM layout for k_mma_multi
#define MM_ROWMAP 0
#define MM_ASH    512
#define MM_ASL    18944
#define MM_BSH    37376
#define MM_BSL    55808
#define MM_TOT    74240
#define WP 36
#define CP 132

// ---------------- unified bf16x3 GEMM body -----------------------------------
struct Job {
    const float* A;
    const float* W;
    const float* bias;
    float* C;
    int typed;
    int type;
};
struct Jobs9 { Job j[9]; };

__device__ __forceinline__ void mma_body(
    const float* __restrict__ A, const float* __restrict__ W,
    const float* __restrict__ bias, float* __restrict__ C,
    char* smem)
{
    int* rowmap = (int*)(smem + MM_ROWMAP);
    uint32_t* Ash = (uint32_t*)(smem + MM_ASH);
    uint32_t* Asl = (uint32_t*)(smem + MM_ASL);
    uint32_t* Bsh = (uint32_t*)(smem + MM_BSH);
    uint32_t* Bsl = (uint32_t*)(smem + MM_BSL);
    float* Cs = (float*)(smem + MM_ASH);

    int tid = threadIdx.x;
    int lane = tid & 31;
    int warp = tid >> 5;
    int warpM = warp >> 1, warpN = warp & 1;
    int g8 = lane >> 2, t4 = lane & 3;

    float acc[2][8][4];
#pragma unroll
    for (int mt = 0; mt < 2; mt++)
#pragma unroll
        for (int nt = 0; nt < 8; nt++)
#pragma unroll
            for (int c = 0; c < 4; c++) acc[mt][nt][c] = 0.0f;

#pragma unroll 1
    for (int kb = 0; kb < 2; kb++) {
        __syncthreads();
#pragma unroll
        for (int j = 0; j < 8; j++) {
            int id = tid + 256 * j;
            int r = id >> 4, k4 = id & 15;
            int node = rowmap[r];
            float4 v = make_float4(0.f, 0.f, 0.f, 0.f);
            if (node >= 0) v = *(const float4*)&A[(long long)node * 128 + kb * 64 + k4 * 4];
            uint32_t h01, l01, h23, l23;
            split2_bf16(v.x, v.y, h01, l01);
            split2_bf16(v.z, v.w, h23, l23);
            *(uint2*)&Ash[r * WP + k4 * 2] = make_uint2(h01, h23);
            *(uint2*)&Asl[r * WP + k4 * 2] = make_uint2(l01, l23);
        }
#pragma unroll
        for (int j = 0; j < 8; j++) {
            int id = tid + 256 * j;
            int n = id & 127, kg = id >> 7;
            const float* Wk = W + (long long)(kb * 64 + kg * 4) * 128 + n;
            float x0 = Wk[0], x1 = Wk[128], x2 = Wk[256], x3 = Wk[384];
            uint32_t h01, l01, h23, l23;
            split2_bf16(x0, x1, h01, l01);
            split2_bf16(x2, x3, h23, l23);
            *(uint2*)&Bsh[n * WP + kg * 2] = make_uint2(h01, h23);
            *(uint2*)&Bsl[n * WP + kg * 2] = make_uint2(l01, l23);
        }
        __syncthreads();

#pragma unroll
        for (int ks = 0; ks < 4; ks++) {
            int ub = ks * 8 + t4;
            uint32_t ah[2][4], al[2][4];
#pragma unroll
            for (int mt = 0; mt < 2; mt++) {
                int rb = warpM * 32 + mt * 16 + g8;
                int base = rb * WP + ub;
                ah[mt][0] = Ash[base];
                ah[mt][1] = Ash[base + 8 * WP];
                ah[mt][2] = Ash[base + 4];
                ah[mt][3] = Ash[base + 8 * WP + 4];
                al[mt][0] = Asl[base];
                al[mt][1] = Asl[base + 8 * WP];
                al[mt][2] = Asl[base + 4];
                al[mt][3] = Asl[base + 8 * WP + 4];
            }
#pragma unroll
            for (int nt = 0; nt < 8; nt++) {
                int nb = warpN * 64 + nt * 8 + g8;
                int bbase = nb * WP + ub;
                uint32_t bh0 = Bsh[bbase], bh1 = Bsh[bbase + 4];
                uint32_t bl0 = Bsl[bbase], bl1 = Bsl[bbase + 4];
                mma_bf16(acc[0][nt], ah[0], bh0, bh1);
                mma_bf16(acc[1][nt], ah[1], bh0, bh1);
                mma_bf16(acc[0][nt], ah[0], bl0, bl1);
                mma_bf16(acc[1][nt], ah[1], bl0, bl1);
                mma_bf16(acc[0][nt], al[0], bh0, bh1);
                mma_bf16(acc[1][nt], al[1], bh0, bh1);
            }
        }
    }

    __syncthreads();
#pragma unroll
    for (int mt = 0; mt < 2; mt++) {
        int r0 = warpM * 32 + mt * 16 + g8;
#pragma unroll
        for (int nt = 0; nt < 8; nt++) {
            int cc = warpN * 64 + nt * 8 + 2 * t4;
            Cs[r0 * CP + cc]           = acc[mt][nt][0];
            Cs[r0 * CP + cc + 1]       = acc[mt][nt][1];
            Cs[(r0 + 8) * CP + cc]     = acc[mt][nt][2];
            Cs[(r0 + 8) * CP + cc + 1] = acc[mt][nt][3];
        }
    }
    __syncthreads();
#pragma unroll
    for (int j = 0; j < 16; j++) {
        int id = tid + 256 * j;
        int r = id >> 5, c4 = id & 31;
        int node = rowmap[r];
        if (node >= 0) {
            float4 v = *(const float4*)&Cs[r * CP + c4 * 4];
            if (bias) {
                v.x += bias[c4 * 4 + 0]; v.y += bias[c4 * 4 + 1];
                v.z += bias[c4 * 4 + 2]; v.w += bias[c4 * 4 + 3];
            }
            *(float4*)&C[(long long)node * 128 + c4 * 4] = v;
        }
    }
}

__global__ void __launch_bounds__(256) k_mma_multi(Jobs9 jobs)
{
    extern __shared__ char smem[];
    Job jb = jobs.j[blockIdx.y];
    int row0, rend;
    if (jb.typed) {
        row0 = g_toff[jb.type] + blockIdx.x * 128;
        rend = g_toff[jb.type + 1];
    } else {
        row0 = blockIdx.x * 128;
        rend = Nn;
    }
    if (row0 >= rend) return;

    int* rowmap = (int*)(smem + MM_ROWMAP);
    if (threadIdx.x < 128) {
        int gr = row0 + threadIdx.x;
        int node = -1;
        if (gr < rend) node = jb.typed ? g_perm[gr] : gr;
        rowmap[threadIdx.x] = node;
    }
    mma_body(jb.A, jb.W, jb.bias, jb.C, smem);
}

// ---------------- per-head knr kernel: kn_h[40000,32] @ [32,160] -------------
// blockIdx.y = head. Output cols: (r, dm) -> g_knr[r][node][h*32+dm].
#define WPR 20
#define R4_ASH  512
#define R4_ASL  (512 + 128 * WPR * 4)
#define R4_BSH  (512 + 2 * 128 * WPR * 4)
#define R4_BSL  (512 + 2 * 128 * WPR * 4 + 160 * WPR * 4)
#define R4_TOT  (512 + 2 * 128 * WPR * 4 + 2 * 160 * WPR * 4)

__global__ void __launch_bounds__(256) k_mma_rel4(
    const float* __restrict__ kn, const float* __restrict__ rel,
    float* __restrict__ knr)
{
    extern __shared__ char smem[];
    int* rowmap = (int*)(smem + 0);
    uint32_t* Ash = (uint32_t*)(smem + R4_ASH);
    uint32_t* Asl = (uint32_t*)(smem + R4_ASL);
    uint32_t* Bsh = (uint32_t*)(smem + R4_BSH);
    uint32_t* Bsl = (uint32_t*)(smem + R4_BSL);

    int tid = threadIdx.x;
    int lane = tid & 31;
    int warp = tid >> 5;
    int warpM = warp >> 1, warpN = warp & 1;
    int g8 = lane >> 2, t4 = lane & 3;
    int h = blockIdx.y;
    int row0 = blockIdx.x * 128;
    if (row0 >= Nn) return;

    if (tid < 128) {
        int gr = row0 + tid;
        rowmap[tid] = (gr < Nn) ? gr : -1;
    }
    __syncthreads();

    // stage A: 128 rows x 16 k-pairs (head slice of kn)
#pragma unroll
    for (int j = 0; j < 8; j++) {
        int id = tid + 256 * j;                  // 2048
        int r = id >> 4, kp = id & 15;
        int node = rowmap[r];
        float2 v = make_float2(0.f, 0.f);
        if (node >= 0) v = *(const float2*)&kn[(long long)node * 128 + h * 32 + 2 * kp];
        uint32_t hi, lo;
        split2_bf16(v.x, v.y, hi, lo);
        Ash[r * WPR + kp] = hi;
        Asl[r * WPR + kp] = lo;
    }
    // stage B: 160 cols (r, dm) x 16 k-pairs: B[col][kp] = rel[r][h][2kp..][dm]
#pragma unroll
    for (int j = 0; j < 10; j++) {
        int id = tid + 256 * j;                  // 2560
        int col = id % 160, kp = id / 160;
        int r_ = col >> 5, dm = col & 31;
        const float* Rp = rel + r_ * 4096 + h * 1024;
        float x = Rp[(2 * kp) * 32 + dm];
        float y = Rp[(2 * kp + 1) * 32 + dm];
        uint32_t hi, lo;
        split2_bf16(x, y, hi, lo);
        Bsh[col * WPR + kp] = hi;
        Bsl[col * WPR + kp] = lo;
    }
    __syncthreads();

    float acc[2][10][4];
#pragma unroll
    for (int mt = 0; mt < 2; mt++)
#pragma unroll
        for (int nt = 0; nt < 10; nt++)
#pragma unroll
            for (int c = 0; c < 4; c++) acc[mt][nt][c] = 0.0f;

#pragma unroll
    for (int ks = 0; ks < 2; ks++) {
        int ub = ks * 8 + t4;
        uint32_t ah[2][4], al[2][4];
#pragma unroll
        for (int mt = 0; mt < 2; mt++) {
            int rb = warpM * 32 + mt * 16 + g8;
            int base = rb * WPR + ub;
            ah[mt][0] = Ash[base];
            ah[mt][1] = Ash[base + 8 * WPR];
            ah[mt][2] = Ash[base + 4];
            ah[mt][3] = Ash[base + 8 * WPR + 4];
            al[mt][0] = Asl[base];
            al[mt][1] = Asl[base + 8 * WPR];
            al[mt][2] = Asl[base + 4];
            al[mt][3] = Asl[base + 8 * WPR + 4];
        }
#pragma unroll
        for (int nt = 0; nt < 10; nt++) {
            int nb = warpN * 80 + nt * 8 + g8;
            int bbase = nb * WPR + ub;
            uint32_t bh0 = Bsh[bbase], bh1 = Bsh[bbase + 4];
            uint32_t bl0 = Bsl[bbase], bl1 = Bsl[bbase + 4];
            mma_bf16(acc[0][nt], ah[0], bh0, bh1);
            mma_bf16(acc[1][nt], ah[1], bh0, bh1);
            mma_bf16(acc[0][nt], ah[0], bl0, bl1);
            mma_bf16(acc[1][nt], ah[1], bl0, bl1);
            mma_bf16(acc[0][nt], al[0], bh0, bh1);
            mma_bf16(acc[1][nt], al[1], bh0, bh1);
        }
    }

    // direct epilogue: float2 stores into per-r planes
#pragma unroll
    for (int mt = 0; mt < 2; mt++) {
        int r0 = warpM * 32 + mt * 16 + g8;
        int node0 = rowmap[r0], node1 = rowmap[r0 + 8];
#pragma unroll
        for (int nt = 0; nt < 10; nt++) {
            int cc = warpN * 80 + nt * 8 + 2 * t4;
            int rr = cc >> 5, dm = cc & 31;
            if (node0 >= 0)
                *(float2*)&knr[(long long)rr * ND + (long long)node0 * 128 + h * 32 + dm] =
                    make_float2(acc[mt][nt][0], acc[mt][nt][1]);
            if (node1 >= 0)
                *(float2*)&knr[(long long)rr * ND + (long long)node1 * 128 + h * 32 + dm] =
                    make_float2(acc[mt][nt][2], acc[mt][nt][3]);
        }
    }
}

// ---------------- setup ----------------
__global__ void k_init() {
    int tid = blockIdx.x * 256 + threadIdx.x;
    if (tid < NH) { g_mx[tid] = __int_as_float(0xff800000); g_den[tid] = 0.0f; }
    if (tid < Nn) g_deg[tid] = 0;
    if (tid < Tt) { g_tcount[tid] = 0; g_cursor[tid] = 0; }
}
__global__ void k_count(const int* __restrict__ node_type, const int* __restrict__ ei) {
    int tid = blockIdx.x * 256 + threadIdx.x;
    if (tid < Nn) atomicAdd(&g_tcount[node_type[tid]], 1);
    if (tid < Ee) atomicAdd(&g_deg[ei[Ee + tid]], 1);
}
__global__ void k_scan() {
    if (threadIdx.x == 0 && blockIdx.x == 0) {
        g_toff[0] = 0;
        for (int t = 0; t < Tt; t++) g_toff[t + 1] = g_toff[t] + g_tcount[t];
    }
}
__global__ void k_scatter(const int* __restrict__ node_type) {
    __shared__ int cnt[Tt], base[Tt];
    if (threadIdx.x < Tt) cnt[threadIdx.x] = 0;
    __syncthreads();
    int n = blockIdx.x * 256 + threadIdx.x;
    int t = -1, lp = 0;
    if (n < Nn) {
        t = node_type[n];
        lp = atomicAdd(&cnt[t], 1);
    }
    __syncthreads();
    if (threadIdx.x < Tt)
        base[threadIdx.x] = atomicAdd(&g_cursor[threadIdx.x], cnt[threadIdx.x]);
    __syncthreads();
    if (n < Nn)
        g_perm[g_toff[t] + base[t] + lp] = n;
}

// ---------------- FFMA2 GEMM (tiny weight-product GEMMs) --------------------
#define GEMM_INNER(AS, BS)                                                   \
    _Pragma("unroll")                                                        \
    for (int k = 0; k < 32; k++) {                                           \
        const float4 av = *(const float4*)&AS;                               \
        ull a0 = dup2(av.x), a1 = dup2(av.y), a2 = dup2(av.z), a3 = dup2(av.w); \
        _Pragma("unroll")                                                    \
        for (int j4 = 0; j4 < 4; j4++) {                                     \
            const float4 bv = *(const float4*)&BS;                           \
            ull b0 = pack2(bv.x, bv.y), b1 = pack2(bv.z, bv.w);              \
            fma2(acc[0][2*j4], a0, b0); fma2(acc[0][2*j4+1], a0, b1);        \
            fma2(acc[1][2*j4], a1, b0); fma2(acc[1][2*j4+1], a1, b1);        \
            fma2(acc[2][2*j4], a2, b0); fma2(acc[2][2*j4+1], a2, b1);        \
            fma2(acc[3][2*j4], a3, b0); fma2(acc[3][2*j4+1], a3, b1);        \
        }                                                                    \
    }

__global__ void __launch_bounds__(256) k_gemm2(
    const float* __restrict__ Ab, long long sA,
    const float* __restrict__ Bb, long long sB,
    const float* __restrict__ biasb, long long sBias,
    float* __restrict__ Cb, long long sC, int M)
{
    const float* A = Ab + (long long)blockIdx.z * sA;
    const float* B = Bb + (long long)blockIdx.z * sB;
    const float* bias = biasb ? (biasb + (long long)blockIdx.z * sBias) : nullptr;
    float* C = Cb + (long long)blockIdx.z * sC;
    int row0 = blockIdx.x * 128;
    if (row0 >= M) return;

    __shared__ float Bs[32][132];
    __shared__ float AsT[32][132];
    int tid = threadIdx.x;
    int tr = tid >> 3, tc = tid & 7;

    ull acc[4][8];
#pragma unroll
    for (int i = 0; i < 4; i++)
#pragma unroll
        for (int j = 0; j < 8; j++) acc[i][j] = 0ULL;

#pragma unroll 1
    for (int kc = 0; kc < 4; kc++) {
        __syncthreads();
#pragma unroll
        for (int j = 0; j < 4; j++) {
            int id = tid + 256 * j;
            int brow = id >> 5, bc = id & 31;
            float4 v = *(const float4*)&B[(kc * 32 + brow) * 128 + bc * 4];
            *(float4*)&Bs[brow][(bc & 3) * 32 + (bc >> 2) * 4] = v;
        }
#pragma unroll
        for (int j = 0; j < 4; j++) {
            int id = tid + 256 * j;
            int arow = id >> 3, a4 = id & 7;
            int grow = row0 + arow;
            float4 v = make_float4(0.f, 0.f, 0.f, 0.f);
            if (grow < M) v = *(const float4*)&A[(long long)grow * 128 + kc * 32 + a4 * 4];
            AsT[a4 * 4 + 0][arow] = v.x;
            AsT[a4 * 4 + 1][arow] = v.y;
            AsT[a4 * 4 + 2][arow] = v.z;
            AsT[a4 * 4 + 3][arow] = v.w;
        }
        __syncthreads();
        GEMM_INNER(AsT[k][tr * 4], Bs[k][j4 * 32 + tc * 4])
    }

#pragma unroll
    for (int i = 0; i < 4; i++) {
        int grow = row0 + tr * 4 + i;
        if (grow < M) {
#pragma unroll
            for (int j4 = 0; j4 < 4; j4++) {
                float2 u0 = unpack2(acc[i][2 * j4]);
                float2 u1 = unpack2(acc[i][2 * j4 + 1]);
                int col = tc * 16 + j4 * 4;
                float4 o = make_float4(u0.x, u0.y, u1.x, u1.y);
                if (bias) {
                    o.x += bias[col]; o.y += bias[col + 1];
                    o.z += bias[col + 2]; o.w += bias[col + 3];
                }
                *(float4*)&C[(long long)grow * 128 + col] = o;
            }
        }
    }
}

// ---------------- tiny precompute kernels -----------------------------------
__global__ void k_bfront(const float* __restrict__ Wak, const float* __restrict__ bq) {
    int kk = blockIdx.x, j = threadIdx.x;
    float s = 0.f;
#pragma unroll 4
    for (int d = 0; d < 128; d++)
        s = fmaf(bq[d], Wak[kk * 16384 + d * 128 + j], s);
    g_bfront[kk * 128 + j] = s;
}

__global__ void k_transpose3() {
    int k = blockIdx.y;
    int id = blockIdx.x * 256 + threadIdx.x;
    if (id < 16384) {
        int i = id >> 7, d = id & 127;
        g_wcombT[k * 16384 + d * 128 + i] = g_wcomb[k * 16384 + i * 128 + d];
    }
}

// b2[k][i] = wcomb[k][i]·bkl ; c3[k][e] = wmkl[k][e]·bfront[k] ; sD[k] = bfront·bkl
__global__ void k_vecs(const float* __restrict__ bkl) {
    int k = blockIdx.x, i = threadIdx.x;
    float s = 0.f, c = 0.f;
#pragma unroll 4
    for (int d = 0; d < 128; d++) {
        s = fmaf(g_wcomb[k * 16384 + i * 128 + d], bkl[d], s);
        c = fmaf(g_wmkl[k * 16384 + i * 128 + d], g_bfront[k * 128 + d], c);
    }
    g_b2[k * 128 + i] = s;
    g_c3[k * 128 + i] = c;
    if (i == 0) {
        float t = 0.f;
        for (int d = 0; d < 128; d++) t = fmaf(g_bfront[k * 128 + d], bkl[d], t);
        g_sD[k] = t;
    }
}

// ---------------- edge logits + segment max (thread per edge-head) ----------
__global__ void __launch_bounds__(256) k_logits4(
    const int* __restrict__ ei, const int* __restrict__ et,
    const float* __restrict__ rel_pri)
{
    int tid = blockIdx.x * 256 + threadIdx.x;
    if (tid >= EH) return;
    int e = tid >> 2, h = tid & 3;
    int s = ei[e], t = ei[Ee + e], r = et[e];
    const float4* q = (const float4*)(g_qn + (long long)t * 128 + h * 32);
    const float4* kk = (const float4*)(g_knr + ((long long)r * Nn + s) * 128 + h * 32);
    float a0 = 0.f, a1 = 0.f;
#pragma unroll
    for (int i = 0; i < 8; i += 2) {
        float4 x = q[i], y = kk[i];
        a0 += x.x * y.x + x.y * y.y + x.z * y.z + x.w * y.w;
        float4 x1 = q[i + 1], y1 = kk[i + 1];
        a1 += x1.x * y1.x + x1.y * y1.y + x1.z * y1.z + x1.w * y1.w;
    }
    float lg = (a0 + a1) * rel_pri[r * 4 + h] * 0.17677669529663687f;
    g_ex[tid] = lg;
    atomicMaxF(&g_mx[t * 4 + h], lg);
}

// ---------------- exp + denominator (one thread per edge) -------------------
__global__ void k_expden4(const int* __restrict__ ei) {
    int e = blockIdx.x * 256 + threadIdx.x;
    if (e >= Ee) return;
    int t = ei[Ee + e];
    float4 lg = *(const float4*)&g_ex[e * 4];
    float4 m = *(const float4*)&g_mx[t * 4];
    float4 v;
    v.x = expf(lg.x - m.x);
    v.y = expf(lg.y - m.y);
    v.z = expf(lg.z - m.z);
    v.w = expf(lg.w - m.w);
    *(float4*)&g_ex[e * 4] = v;
    atomicAdd(&g_den[t * 4 + 0], v.x);
    atomicAdd(&g_den[t * 4 + 1], v.y);
    atomicAdd(&g_den[t * 4 + 2], v.z);
    atomicAdd(&g_den[t * 4 + 3], v.w);
}

// ---------------- messages (only edge ids < N matter) -----------------------
__global__ void __launch_bounds__(256) k_msg(
    const int* __restrict__ ei, const int* __restrict__ et,
    const float* __restrict__ rel_msg)
{
    extern __shared__ float sh[];
    float* relS = sh;
    float* vnS = sh + RELF;
    for (int i = threadIdx.x; i < RELF; i += 256) relS[i] = rel_msg[i];
    __syncthreads();

    int warp = threadIdx.x >> 5, lane = threadIdx.x & 31;
    float* vW = vnS + warp * 128;
    int stride = gridDim.x * 8;
    for (int n = blockIdx.x * 8 + warp; n < Nn; n += stride) {
        int s = ei[n], t = ei[Ee + n], r = et[n];
        __syncwarp();
#pragma unroll
        for (int h = 0; h < 4; h++)
            vW[h * 32 + lane] = g_vn[(long long)s * 128 + h * 32 + lane];
        __syncwarp();
        float deg = (float)g_deg[n];
#pragma unroll
        for (int h = 0; h < 4; h++) {
            float att = g_ex[n * 4 + h] / (g_den[t * 4 + h] + 1e-16f);
            const float* Am = relS + (r * 4 + h) * 1024;
            float a0 = 0.f, a1 = 0.f;
#pragma unroll
            for (int d = 0; d < 32; d += 2) {
                a0 = fmaf(vW[h * 32 + d],     Am[d * 32 + lane],       a0);
                a1 = fmaf(vW[h * 32 + d + 1], Am[(d + 1) * 32 + lane], a1);
            }
            float vp = a0 + a1;
            float c = att * deg;
            long long o = (long long)n * 128 + h * 32 + lane;
            float m1 = vp * c;
            float m2 = vp * vp * c;
            float m3 = vp * vp * vp * c;
            float s3 = (m3 > 0.f) ? 1.f : ((m3 < 0.f) ? -1.f : 0.f);
            float r3 = s3 * powf(fabsf(m3) + 1e-18f, 0.33333333333333333f);
            g_agg[o] = m1;
            g_agg[ND + o] = m2;
            g_agg[2 * ND + o] = r3;
        }
    }
}

// ---------------- gating + residual + gelu (bilinear form) ------------------
// s_k[n] = meta[n]·u_k[n] + agg_k[n]·c3[k] + sD[k]
__global__ void __launch_bounds__(256) k_res(const float* __restrict__ meta) {
    int warp = threadIdx.x >> 5, lane = threadIdx.x & 31;
    int n = blockIdx.x * 8 + warp;
    if (n >= Nn) return;
    long long base = (long long)n * 128 + lane * 4;
    const float4 m4 = *(const float4*)&meta[base];
    float r0 = 0.f, r1 = 0.f, r2 = 0.f, r3 = 0.f;
#pragma unroll
    for (int kk = 0; kk < 3; kk++) {
        const float4 u4 = *(const float4*)&g_u[kk * ND + base];
        const float4 a4 = *(const float4*)&g_agg[kk * ND + base];
        const float4 c4 = *(const float4*)&g_c3[kk * 128 + lane * 4];
        float p = m4.x * u4.x + m4.y * u4.y + m4.z * u4.z + m4.w * u4.w
                + a4.x * c4.x + a4.y * c4.y + a4.z * c4.z + a4.w * c4.w;
#pragma unroll
        for (int o = 16; o > 0; o >>= 1) p += __shfl_xor_sync(0xffffffffu, p, o);
        float tt = sigmoidf_(p + g_sD[kk]);
        const float4 am = *(const float4*)&g_aggm[kk * ND + base];
        r0 = fmaf(tt, am.x, r0);
        r1 = fmaf(tt, am.y, r1);
        r2 = fmaf(tt, am.z, r2);
        r3 = fmaf(tt, am.w, r3);
    }
    float4 o;
    o.x = 0.5f * r0 * (1.0f + erff(r0 * 0.70710678118654752f));
    o.y = 0.5f * r1 * (1.0f + erff(r1 * 0.70710678118654752f));
    o.z = 0.5f * r2 * (1.0f + erff(r2 * 0.70710678118654752f));
    o.w = 0.5f * r3 * (1.0f + erff(r3 * 0.70710678118654752f));
    *(float4*)&g_hbuf[base] = o;
}

// ---------------- skip-mix + per-type LayerNorm -----------------------------
__global__ void __launch_bounds__(256) k_final(
    const float* __restrict__ meta, const int* __restrict__ node_type,
    const float* __restrict__ skip, const float* __restrict__ ln_g,
    const float* __restrict__ ln_b, float* __restrict__ out)
{
    int warp = threadIdx.x >> 5, lane = threadIdx.x & 31;
    int n = blockIdx.x * 8 + warp;
    if (n >= Nn) return;
    int t = node_type[n];
    float alpha = sigmoidf_(skip[t]);
    long long base = (long long)n * 128 + lane * 4;
    const float4 tr = *(const float4*)&g_trans[base];
    const float4 x = *(const float4*)&meta[base];
    float y0 = tr.x * alpha + x.x * (1.0f - alpha);
    float y1 = tr.y * alpha + x.y * (1.0f - alpha);
    float y2 = tr.z * alpha + x.z * (1.0f - alpha);
    float y3 = tr.w * alpha + x.w * (1.0f - alpha);
    float s = y0 + y1 + y2 + y3;
    float sq = y0 * y0 + y1 * y1 + y2 * y2 + y3 * y3;
#pragma unroll
    for (int o = 16; o > 0; o >>= 1) {
        s += __shfl_xor_sync(0xffffffffu, s, o);
        sq += __shfl_xor_sync(0xffffffffu, sq, o);
    }
    float mu = s * (1.0f / 128.0f);
    float var = sq * (1.0f / 128.0f) - mu * mu;
    float inv = 1.0f / sqrtf(var + 1e-5f);
    int c = lane * 4;
    const float4 g = *(const float4*)&ln_g[t * 128 + c];
    const float4 b = *(const float4*)&ln_b[t * 128 + c];
    float4 o;
    o.x = (y0 - mu) * inv * g.x + b.x;
    o.y = (y1 - mu) * inv * g.y + b.y;
    o.z = (y2 - mu) * inv * g.z + b.z;
    o.w = (y3 - mu) * inv * g.w + b.w;
    *(float4*)&out[base] = o;
}

// ---------------- host launcher ---------------------------------------------
extern "C" void kernel_launch(void* const* d_in, const int* in_sizes, int n_in,
                              void* d_out, int out_size)
{
    const float* meta      = (const float*)d_in[0];
    const int*   node_type = (const int*)d_in[1];
    const int*   ei        = (const int*)d_in[2];
    const int*   etype     = (const int*)d_in[3];
    const float* q_w = (const float*)d_in[5];
    const float* q_b = (const float*)d_in[6];
    const float* k_w = (const float*)d_in[7];
    const float* k_b = (const float*)d_in[8];
    const float* v_w = (const float*)d_in[9];
    const float* v_b = (const float*)d_in[10];
    const float* a_w = (const float*)d_in[11];
    const float* a_b = (const float*)d_in[12];
    const float* rel_pri = (const float*)d_in[13];
    const float* rel_att = (const float*)d_in[14];
    const float* rel_msg = (const float*)d_in[15];
    const float* WMk = (const float*)d_in[16];
    const float* Wak = (const float*)d_in[17];
    const float* Wq  = (const float*)d_in[18];
    const float* bq  = (const float*)d_in[19];
    const float* Wkl = (const float*)d_in[20];
    const float* bkl = (const float*)d_in[21];
    const float* skip = (const float*)d_in[22];
    const float* ln_g = (const float*)d_in[23];
    const float* ln_b = (const float*)d_in[24];
    float* out = (float*)d_out;

    float *p_qn, *p_kn, *p_vn, *p_knr, *p_agg, *p_aggm, *p_u, *p_hbuf, *p_trans,
          *p_wcomb, *p_wcombT, *p_wmkl, *p_GT, *p_bfront, *p_b2;
    cudaGetSymbolAddress((void**)&p_qn, g_qn);
    cudaGetSymbolAddress((void**)&p_kn, g_kn);
    cudaGetSymbolAddress((void**)&p_vn, g_vn);
    cudaGetSymbolAddress((void**)&p_knr, g_knr);
    cudaGetSymbolAddress((void**)&p_agg, g_agg);
    cudaGetSymbolAddress((void**)&p_aggm, g_aggm);
    cudaGetSymbolAddress((void**)&p_u, g_u);
    cudaGetSymbolAddress((void**)&p_hbuf, g_hbuf);
    cudaGetSymbolAddress((void**)&p_trans, g_trans);
    cudaGetSymbolAddress((void**)&p_wcomb, g_wcomb);
    cudaGetSymbolAddress((void**)&p_wcombT, g_wcombT);
    cudaGetSymbolAddress((void**)&p_wmkl, g_wmkl);
    cudaGetSymbolAddress((void**)&p_GT, g_GT);
    cudaGetSymbolAddress((void**)&p_bfront, g_bfront);
    cudaGetSymbolAddress((void**)&p_b2, g_b2);

    const int SMEM_EDGE = (RELF + 8 * 128) * 4;               // 86016 B
    cudaFuncSetAttribute(k_msg, cudaFuncAttributeMaxDynamicSharedMemorySize, SMEM_EDGE);
    cudaFuncSetAttribute(k_mma_multi, cudaFuncAttributeMaxDynamicSharedMemorySize, MM_TOT);
    cudaFuncSetAttribute(k_mma_rel4, cudaFuncAttributeMaxDynamicSharedMemorySize, R4_TOT);

    dim3 blk(256);
    const int GB = 313;   // ceil(40000/128)

    k_init<<<625, blk>>>();
    k_count<<<1250, blk>>>(node_type, ei);
    k_scan<<<1, 32>>>();
    k_scatter<<<157, blk>>>(node_type);

    // tiny weight products
    k_gemm2<<<dim3(1, 1, 3), blk>>>(Wq, 0, Wak, 16384, nullptr, 0, p_wcomb, 16384, 128);
    k_gemm2<<<dim3(1, 1, 3), blk>>>(WMk, 16384, Wkl, 0, nullptr, 0, p_wmkl, 16384, 128);
    k_bfront<<<3, 128>>>(Wak, bq);
    k_transpose3<<<dim3(64, 3), blk>>>();
    // GT[k] = wmkl[k] @ wcombT[k]
    k_gemm2<<<dim3(1, 1, 3), blk>>>(p_wmkl, 16384, p_wcombT, 16384, nullptr, 0, p_GT, 16384, 128);
    k_vecs<<<3, 128>>>(bkl);

    // merged q/k/v typed projections: 9 jobs
    {
        Jobs9 J;
        const float* Ws[3] = {q_w, k_w, v_w};
        const float* Bs_[3] = {q_b, k_b, v_b};
        float* Cs_[3] = {p_qn, p_kn, p_vn};
        for (int m = 0; m < 3; m++)
            for (int t = 0; t < 3; t++)
                J.j[m * 3 + t] = Job{meta, Ws[m] + (long long)t * 16384,
                                     Bs_[m] + (long long)t * 128, Cs_[m], 1, t};
        k_mma_multi<<<dim3(GB, 9), blk, MM_TOT>>>(J);
    }

    // knr per-head: [40000,32] @ [32,160] x 4 heads
    k_mma_rel4<<<dim3(GB, 4), blk, R4_TOT>>>(p_kn, rel_att, p_knr);

    // logits + segment max; exp + denominators
    k_logits4<<<5000, blk>>>(ei, etype, rel_pri);
    k_expden4<<<1250, blk>>>(ei);

    // messages for edge ids < N
    k_msg<<<296, blk, SMEM_EDGE>>>(ei, etype, rel_msg);

    // merged aggm / u: 6 dense jobs
    // aggm[k] = agg[k] @ WMk[k]
    // u[k]    = agg[k] @ GT[k] + b2[k]
    {
        Jobs9 J;
        for (int kk = 0; kk < 3; kk++) {
            J.j[kk]     = Job{p_agg + (long long)kk * ND, WMk + (long long)kk * 16384,
                              nullptr, p_aggm + (long long)kk * ND, 0, 0};
            J.j[3 + kk] = Job{p_agg + (long long)kk * ND, p_GT + (long long)kk * 16384,
                              p_b2 + (long long)kk * 128, p_u + (long long)kk * ND, 0, 0};
        }
        for (int z = 6; z < 9; z++) J.j[z] = J.j[0];
        k_mma_multi<<<dim3(GB, 6), blk, MM_TOT>>>(J);
    }

    k_res<<<5000, blk>>>(meta);

    // trans = typed(gelu(res), a_w, a_b): 3 typed jobs
    {
        Jobs9 J;
        for (int t = 0; t < 3; t++)
            J.j[t] = Job{p_hbuf, a_w + (long long)t * 16384,
                         a_b + (long long)t * 128, p_trans, 1, t};
        for (int z = 3; z < 9; z++) J.j[z] = J.j[0];
        k_mma_multi<<<dim3(GB, 3), blk, MM_TOT>>>(J);
    }

    k_final<<<5000, blk>>>(meta, node_type, skip, ln_g, ln_b, out);
}

// round 16
// speedup vs baseline: 1.8551x; 1.0152x over previous
#include <cuda_runtime.h>
#include <cuda_bf16.h>
#include <math.h>
#include <stdint.h>

#define Nn 40000
#define Ee 320000
#define Dd 128
#define Hh 4
#define DK 32
#define Tt 3
#define Rr 5
#define Kk 3
#define ND 5120000      // N*D
#define EH 1280000      // E*H
#define NH 160000       // N*H
#define RELF 20480      // R*H*DK*DK floats

typedef unsigned long long ull;

// ---------------- device scratch ----------------
__device__ __align__(16) float g_qn[ND];
__device__ __align__(16) float g_kn[ND];
__device__ __align__(16) float g_vn[ND];
__device__ __align__(16) float g_knr[Rr * ND];   // [r][n][128]
__device__ __align__(16) float g_ex[EH];
__device__ __align__(16) float g_mx[NH];
__device__ __align__(16) float g_den[NH];
__device__ int   g_deg[Nn];
__device__ int   g_perm[Nn];
__device__ int   g_tcount[Tt];
__device__ int   g_toff[Tt + 1];
__device__ int   g_cursor[Tt];
__device__ __align__(16) float g_agg[Kk * ND];
__device__ __align__(16) float g_aggm[Kk * ND];
__device__ __align__(16) float g_u[Kk * ND];      // u[k] = agg[k] @ GT[k] + b2[k]
__device__ __align__(16) float g_hbuf[ND];
__device__ __align__(16) float g_trans[ND];
__device__ __align__(16) float g_wcomb[Kk * 16384];
__device__ __align__(16) float g_wcombT[Kk * 16384];
__device__ __align__(16) float g_wmkl[Kk * 16384];
__device__ __align__(16) float g_GT[Kk * 16384];
__device__ __align__(16) float g_bfront[Kk * 128];
__device__ __align__(16) float g_b2[Kk * 128];
__device__ __align__(16) float g_c3[Kk * 128];
__device__ float g_sD[Kk];

// ---------------- small helpers ----------------
__device__ __forceinline__ float sigmoidf_(float x) { return 1.0f / (1.0f + expf(-x)); }

__device__ __forceinline__ void atomicMaxF(float* addr, float v) {
    int old = __float_as_int(*addr);
    while (__int_as_float(old) < v) {
        int prev = atomicCAS((int*)addr, old, __float_as_int(v));
        if (prev == old) break;
        old = prev;
    }
}

__device__ __forceinline__ void fma2(ull& d, ull a, ull b) {
    asm("fma.rn.f32x2 %0, %1, %2, %0;" : "+l"(d) : "l"(a), "l"(b));
}
__device__ __forceinline__ ull dup2(float x) {
    ull r; asm("mov.b64 %0, {%1, %1};" : "=l"(r) : "f"(x)); return r;
}
__device__ __forceinline__ ull pack2(float x, float y) {
    ull r; asm("mov.b64 %0, {%1, %2};" : "=l"(r) : "f"(x), "f"(y)); return r;
}
__device__ __forceinline__ float2 unpack2(ull v) {
    float2 f; asm("mov.b64 {%0, %1}, %2;" : "=f"(f.x), "=f"(f.y) : "l"(v)); return f;
}

__device__ __forceinline__ uint32_t pack_bf16(float x, float y) {
    uint32_t r; asm("cvt.rn.bf16x2.f32 %0, %1, %2;" : "=r"(r) : "f"(y), "f"(x));
    return r;
}
__device__ __forceinline__ void split2_bf16(float x, float y, uint32_t& hi, uint32_t& lo) {
    hi = pack_bf16(x, y);
    float rx = x - __uint_as_float(hi << 16);
    float ry = y - __uint_as_float(hi & 0xffff0000u);
    lo = pack_bf16(rx, ry);
}

__device__ __forceinline__ void mma_bf16(float* c, const uint32_t* a,
                                         uint32_t b0, uint32_t b1) {
    asm volatile(
        "mma.sync.aligned.m16n8k16.row.col.f32.bf16.bf16.f32 "
        "{%0,%1,%2,%3}, {%4,%5,%6,%7}, {%8,%9}, {%0,%1,%2,%3};"
        : "+f"(c[0]), "+f"(c[1]), "+f"(c[2]), "+f"(c[3])
        : "r"(a[0]), "r"(a[1]), "r"(a[2]), "r"(a[3]), "r"(b0), "r"(b1));
}

// SMEM layout for k_mma_multi
#define MM_ROWMAP 0
#define MM_ASH    512
#define MM_ASL    18944
#define MM_BSH    37376
#define MM_BSL    55808
#define MM_TOT    74240
#define WP 36
#define CP 132

// ---------------- unified bf16x3 GEMM body -----------------------------------
struct Job {
    const float* A;
    const float* W;
    const float* bias;
    float* C;
    int typed;
    int type;
};
struct Jobs9 { Job j[9]; };

__device__ __forceinline__ void mma_body(
    const float* __restrict__ A, const float* __restrict__ W,
    const float* __restrict__ bias, float* __restrict__ C,
    char* smem)
{
    int* rowmap = (int*)(smem + MM_ROWMAP);
    uint32_t* Ash = (uint32_t*)(smem + MM_ASH);
    uint32_t* Asl = (uint32_t*)(smem + MM_ASL);
    uint32_t* Bsh = (uint32_t*)(smem + MM_BSH);
    uint32_t* Bsl = (uint32_t*)(smem + MM_BSL);
    float* Cs = (float*)(smem + MM_ASH);

    int tid = threadIdx.x;
    int lane = tid & 31;
    int warp = tid >> 5;
    int warpM = warp >> 1, warpN = warp & 1;
    int g8 = lane >> 2, t4 = lane & 3;

    float acc[2][8][4];
#pragma unroll
    for (int mt = 0; mt < 2; mt++)
#pragma unroll
        for (int nt = 0; nt < 8; nt++)
#pragma unroll
            for (int c = 0; c < 4; c++) acc[mt][nt][c] = 0.0f;

#pragma unroll 1
    for (int kb = 0; kb < 2; kb++) {
        __syncthreads();
#pragma unroll
        for (int j = 0; j < 8; j++) {
            int id = tid + 256 * j;
            int r = id >> 4, k4 = id & 15;
            int node = rowmap[r];
            float4 v = make_float4(0.f, 0.f, 0.f, 0.f);
            if (node >= 0) v = *(const float4*)&A[(long long)node * 128 + kb * 64 + k4 * 4];
            uint32_t h01, l01, h23, l23;
            split2_bf16(v.x, v.y, h01, l01);
            split2_bf16(v.z, v.w, h23, l23);
            *(uint2*)&Ash[r * WP + k4 * 2] = make_uint2(h01, h23);
            *(uint2*)&Asl[r * WP + k4 * 2] = make_uint2(l01, l23);
        }
#pragma unroll
        for (int j = 0; j < 8; j++) {
            int id = tid + 256 * j;
            int n = id & 127, kg = id >> 7;
            const float* Wk = W + (long long)(kb * 64 + kg * 4) * 128 + n;
            float x0 = Wk[0], x1 = Wk[128], x2 = Wk[256], x3 = Wk[384];
            uint32_t h01, l01, h23, l23;
            split2_bf16(x0, x1, h01, l01);
            split2_bf16(x2, x3, h23, l23);
            *(uint2*)&Bsh[n * WP + kg * 2] = make_uint2(h01, h23);
            *(uint2*)&Bsl[n * WP + kg * 2] = make_uint2(l01, l23);
        }
        __syncthreads();

#pragma unroll
        for (int ks = 0; ks < 4; ks++) {
            int ub = ks * 8 + t4;
            uint32_t ah[2][4], al[2][4];
#pragma unroll
            for (int mt = 0; mt < 2; mt++) {
                int rb = warpM * 32 + mt * 16 + g8;
                int base = rb * WP + ub;
                ah[mt][0] = Ash[base];
                ah[mt][1] = Ash[base + 8 * WP];
                ah[mt][2] = Ash[base + 4];
                ah[mt][3] = Ash[base + 8 * WP + 4];
                al[mt][0] = Asl[base];
                al[mt][1] = Asl[base + 8 * WP];
                al[mt][2] = Asl[base + 4];
                al[mt][3] = Asl[base + 8 * WP + 4];
            }
#pragma unroll
            for (int nt = 0; nt < 8; nt++) {
                int nb = warpN * 64 + nt * 8 + g8;
                int bbase = nb * WP + ub;
                uint32_t bh0 = Bsh[bbase], bh1 = Bsh[bbase + 4];
                uint32_t bl0 = Bsl[bbase], bl1 = Bsl[bbase + 4];
                mma_bf16(acc[0][nt], ah[0], bh0, bh1);
                mma_bf16(acc[1][nt], ah[1], bh0, bh1);
                mma_bf16(acc[0][nt], ah[0], bl0, bl1);
                mma_bf16(acc[1][nt], ah[1], bl0, bl1);
                mma_bf16(acc[0][nt], al[0], bh0, bh1);
                mma_bf16(acc[1][nt], al[1], bh0, bh1);
            }
        }
    }

    __syncthreads();
#pragma unroll
    for (int mt = 0; mt < 2; mt++) {
        int r0 = warpM * 32 + mt * 16 + g8;
#pragma unroll
        for (int nt = 0; nt < 8; nt++) {
            int cc = warpN * 64 + nt * 8 + 2 * t4;
            Cs[r0 * CP + cc]           = acc[mt][nt][0];
            Cs[r0 * CP + cc + 1]       = acc[mt][nt][1];
            Cs[(r0 + 8) * CP + cc]     = acc[mt][nt][2];
            Cs[(r0 + 8) * CP + cc + 1] = acc[mt][nt][3];
        }
    }
    __syncthreads();
#pragma unroll
    for (int j = 0; j < 16; j++) {
        int id = tid + 256 * j;
        int r = id >> 5, c4 = id & 31;
        int node = rowmap[r];
        if (node >= 0) {
            float4 v = *(const float4*)&Cs[r * CP + c4 * 4];
            if (bias) {
                v.x += bias[c4 * 4 + 0]; v.y += bias[c4 * 4 + 1];
                v.z += bias[c4 * 4 + 2]; v.w += bias[c4 * 4 + 3];
            }
            *(float4*)&C[(long long)node * 128 + c4 * 4] = v;
        }
    }
}

__global__ void __launch_bounds__(256) k_mma_multi(Jobs9 jobs)
{
    extern __shared__ char smem[];
    Job jb = jobs.j[blockIdx.y];
    int row0, rend;
    if (jb.typed) {
        row0 = g_toff[jb.type] + blockIdx.x * 128;
        rend = g_toff[jb.type + 1];
    } else {
        row0 = blockIdx.x * 128;
        rend = Nn;
    }
    if (row0 >= rend) return;

    int* rowmap = (int*)(smem + MM_ROWMAP);
    if (threadIdx.x < 128) {
        int gr = row0 + threadIdx.x;
        int node = -1;
        if (gr < rend) node = jb.typed ? g_perm[gr] : gr;
        rowmap[threadIdx.x] = node;
    }
    mma_body(jb.A, jb.W, jb.bias, jb.C, smem);
}

// ---------------- per-head knr kernel: kn_h[40000,32] @ [32,160] -------------
#define WPR 20
#define R4_ASH  512
#define R4_ASL  (512 + 128 * WPR * 4)
#define R4_BSH  (512 + 2 * 128 * WPR * 4)
#define R4_BSL  (512 + 2 * 128 * WPR * 4 + 160 * WPR * 4)
#define R4_TOT  (512 + 2 * 128 * WPR * 4 + 2 * 160 * WPR * 4)

__global__ void __launch_bounds__(256) k_mma_rel4(
    const float* __restrict__ kn, const float* __restrict__ rel,
    float* __restrict__ knr)
{
    extern __shared__ char smem[];
    int* rowmap = (int*)(smem + 0);
    uint32_t* Ash = (uint32_t*)(smem + R4_ASH);
    uint32_t* Asl = (uint32_t*)(smem + R4_ASL);
    uint32_t* Bsh = (uint32_t*)(smem + R4_BSH);
    uint32_t* Bsl = (uint32_t*)(smem + R4_BSL);

    int tid = threadIdx.x;
    int lane = tid & 31;
    int warp = tid >> 5;
    int warpM = warp >> 1, warpN = warp & 1;
    int g8 = lane >> 2, t4 = lane & 3;
    int h = blockIdx.y;
    int row0 = blockIdx.x * 128;
    if (row0 >= Nn) return;

    if (tid < 128) {
        int gr = row0 + tid;
        rowmap[tid] = (gr < Nn) ? gr : -1;
    }
    __syncthreads();

#pragma unroll
    for (int j = 0; j < 8; j++) {
        int id = tid + 256 * j;
        int r = id >> 4, kp = id & 15;
        int node = rowmap[r];
        float2 v = make_float2(0.f, 0.f);
        if (node >= 0) v = *(const float2*)&kn[(long long)node * 128 + h * 32 + 2 * kp];
        uint32_t hi, lo;
        split2_bf16(v.x, v.y, hi, lo);
        Ash[r * WPR + kp] = hi;
        Asl[r * WPR + kp] = lo;
    }
#pragma unroll
    for (int j = 0; j < 10; j++) {
        int id = tid + 256 * j;
        int col = id % 160, kp = id / 160;
        int r_ = col >> 5, dm = col & 31;
        const float* Rp = rel + r_ * 4096 + h * 1024;
        float x = Rp[(2 * kp) * 32 + dm];
        float y = Rp[(2 * kp + 1) * 32 + dm];
        uint32_t hi, lo;
        split2_bf16(x, y, hi, lo);
        Bsh[col * WPR + kp] = hi;
        Bsl[col * WPR + kp] = lo;
    }
    __syncthreads();

    float acc[2][10][4];
#pragma unroll
    for (int mt = 0; mt < 2; mt++)
#pragma unroll
        for (int nt = 0; nt < 10; nt++)
#pragma unroll
            for (int c = 0; c < 4; c++) acc[mt][nt][c] = 0.0f;

#pragma unroll
    for (int ks = 0; ks < 2; ks++) {
        int ub = ks * 8 + t4;
        uint32_t ah[2][4], al[2][4];
#pragma unroll
        for (int mt = 0; mt < 2; mt++) {
            int rb = warpM * 32 + mt * 16 + g8;
            int base = rb * WPR + ub;
            ah[mt][0] = Ash[base];
            ah[mt][1] = Ash[base + 8 * WPR];
            ah[mt][2] = Ash[base + 4];
            ah[mt][3] = Ash[base + 8 * WPR + 4];
            al[mt][0] = Asl[base];
            al[mt][1] = Asl[base + 8 * WPR];
            al[mt][2] = Asl[base + 4];
            al[mt][3] = Asl[base + 8 * WPR + 4];
        }
#pragma unroll
        for (int nt = 0; nt < 10; nt++) {
            int nb = warpN * 80 + nt * 8 + g8;
            int bbase = nb * WPR + ub;
            uint32_t bh0 = Bsh[bbase], bh1 = Bsh[bbase + 4];
            uint32_t bl0 = Bsl[bbase], bl1 = Bsl[bbase + 4];
            mma_bf16(acc[0][nt], ah[0], bh0, bh1);
            mma_bf16(acc[1][nt], ah[1], bh0, bh1);
            mma_bf16(acc[0][nt], ah[0], bl0, bl1);
            mma_bf16(acc[1][nt], ah[1], bl0, bl1);
            mma_bf16(acc[0][nt], al[0], bh0, bh1);
            mma_bf16(acc[1][nt], al[1], bh0, bh1);
        }
    }

#pragma unroll
    for (int mt = 0; mt < 2; mt++) {
        int r0 = warpM * 32 + mt * 16 + g8;
        int node0 = rowmap[r0], node1 = rowmap[r0 + 8];
#pragma unroll
        for (int nt = 0; nt < 10; nt++) {
            int cc = warpN * 80 + nt * 8 + 2 * t4;
            int rr = cc >> 5, dm = cc & 31;
            if (node0 >= 0)
                *(float2*)&knr[(long long)rr * ND + (long long)node0 * 128 + h * 32 + dm] =
                    make_float2(acc[mt][nt][0], acc[mt][nt][1]);
            if (node1 >= 0)
                *(float2*)&knr[(long long)rr * ND + (long long)node1 * 128 + h * 32 + dm] =
                    make_float2(acc[mt][nt][2], acc[mt][nt][3]);
        }
    }
}

// ---------------- setup ----------------
__global__ void k_init() {
    int tid = blockIdx.x * 256 + threadIdx.x;
    if (tid < NH) { g_mx[tid] = __int_as_float(0xff800000); g_den[tid] = 0.0f; }
    if (tid < Nn) g_deg[tid] = 0;
    if (tid < Tt) { g_tcount[tid] = 0; g_cursor[tid] = 0; }
}
// block-aggregated type counts (same pattern as proven k_scatter fix)
__global__ void k_count(const int* __restrict__ node_type, const int* __restrict__ ei) {
    __shared__ int cnt[Tt];
    if (threadIdx.x < Tt) cnt[threadIdx.x] = 0;
    __syncthreads();
    int tid = blockIdx.x * 256 + threadIdx.x;
    if (tid < Nn) atomicAdd(&cnt[node_type[tid]], 1);
    if (tid < Ee) atomicAdd(&g_deg[ei[Ee + tid]], 1);
    __syncthreads();
    if (threadIdx.x < Tt && cnt[threadIdx.x] > 0)
        atomicAdd(&g_tcount[threadIdx.x], cnt[threadIdx.x]);
}
__global__ void k_scan() {
    if (threadIdx.x == 0 && blockIdx.x == 0) {
        g_toff[0] = 0;
        for (int t = 0; t < Tt; t++) g_toff[t + 1] = g_toff[t] + g_tcount[t];
    }
}
__global__ void k_scatter(const int* __restrict__ node_type) {
    __shared__ int cnt[Tt], base[Tt];
    if (threadIdx.x < Tt) cnt[threadIdx.x] = 0;
    __syncthreads();
    int n = blockIdx.x * 256 + threadIdx.x;
    int t = -1, lp = 0;
    if (n < Nn) {
        t = node_type[n];
        lp = atomicAdd(&cnt[t], 1);
    }
    __syncthreads();
    if (threadIdx.x < Tt)
        base[threadIdx.x] = atomicAdd(&g_cursor[threadIdx.x], cnt[threadIdx.x]);
    __syncthreads();
    if (n < Nn)
        g_perm[g_toff[t] + base[t] + lp] = n;
}

// ---------------- FFMA2 GEMM (tiny weight-product GEMMs) --------------------
#define GEMM_INNER(AS, BS)                                                   \
    _Pragma("unroll")                                                        \
    for (int k = 0; k < 32; k++) {                                           \
        const float4 av = *(const float4*)&AS;                               \
        ull a0 = dup2(av.x), a1 = dup2(av.y), a2 = dup2(av.z), a3 = dup2(av.w); \
        _Pragma("unroll")                                                    \
        for (int j4 = 0; j4 < 4; j4++) {                                     \
            const float4 bv = *(const float4*)&BS;                           \
            ull b0 = pack2(bv.x, bv.y), b1 = pack2(bv.z, bv.w);              \
            fma2(acc[0][2*j4], a0, b0); fma2(acc[0][2*j4+1], a0, b1);        \
            fma2(acc[1][2*j4], a1, b0); fma2(acc[1][2*j4+1], a1, b1);        \
            fma2(acc[2][2*j4], a2, b0); fma2(acc[2][2*j4+1], a2, b1);        \
            fma2(acc[3][2*j4], a3, b0); fma2(acc[3][2*j4+1], a3, b1);        \
        }                                                                    \
    }

__global__ void __launch_bounds__(256) k_gemm2(
    const float* __restrict__ Ab, long long sA,
    const float* __restrict__ Bb, long long sB,
    const float* __restrict__ biasb, long long sBias,
    float* __restrict__ Cb, long long sC, int M)
{
    const float* A = Ab + (long long)blockIdx.z * sA;
    const float* B = Bb + (long long)blockIdx.z * sB;
    const float* bias = biasb ? (biasb + (long long)blockIdx.z * sBias) : nullptr;
    float* C = Cb + (long long)blockIdx.z * sC;
    int row0 = blockIdx.x * 128;
    if (row0 >= M) return;

    __shared__ float Bs[32][132];
    __shared__ float AsT[32][132];
    int tid = threadIdx.x;
    int tr = tid >> 3, tc = tid & 7;

    ull acc[4][8];
#pragma unroll
    for (int i = 0; i < 4; i++)
#pragma unroll
        for (int j = 0; j < 8; j++) acc[i][j] = 0ULL;

#pragma unroll 1
    for (int kc = 0; kc < 4; kc++) {
        __syncthreads();
#pragma unroll
        for (int j = 0; j < 4; j++) {
            int id = tid + 256 * j;
            int brow = id >> 5, bc = id & 31;
            float4 v = *(const float4*)&B[(kc * 32 + brow) * 128 + bc * 4];
            *(float4*)&Bs[brow][(bc & 3) * 32 + (bc >> 2) * 4] = v;
        }
#pragma unroll
        for (int j = 0; j < 4; j++) {
            int id = tid + 256 * j;
            int arow = id >> 3, a4 = id & 7;
            int grow = row0 + arow;
            float4 v = make_float4(0.f, 0.f, 0.f, 0.f);
            if (grow < M) v = *(const float4*)&A[(long long)grow * 128 + kc * 32 + a4 * 4];
            AsT[a4 * 4 + 0][arow] = v.x;
            AsT[a4 * 4 + 1][arow] = v.y;
            AsT[a4 * 4 + 2][arow] = v.z;
            AsT[a4 * 4 + 3][arow] = v.w;
        }
        __syncthreads();
        GEMM_INNER(AsT[k][tr * 4], Bs[k][j4 * 32 + tc * 4])
    }

#pragma unroll
    for (int i = 0; i < 4; i++) {
        int grow = row0 + tr * 4 + i;
        if (grow < M) {
#pragma unroll
            for (int j4 = 0; j4 < 4; j4++) {
                float2 u0 = unpack2(acc[i][2 * j4]);
                float2 u1 = unpack2(acc[i][2 * j4 + 1]);
                int col = tc * 16 + j4 * 4;
                float4 o = make_float4(u0.x, u0.y, u1.x, u1.y);
                if (bias) {
                    o.x += bias[col]; o.y += bias[col + 1];
                    o.z += bias[col + 2]; o.w += bias[col + 3];
                }
                *(float4*)&C[(long long)grow * 128 + col] = o;
            }
        }
    }
}

// ---------------- tiny precompute kernels -----------------------------------
__global__ void k_bfront(const float* __restrict__ Wak, const float* __restrict__ bq) {
    int kk = blockIdx.x, j = threadIdx.x;
    float s = 0.f;
#pragma unroll 4
    for (int d = 0; d < 128; d++)
        s = fmaf(bq[d], Wak[kk * 16384 + d * 128 + j], s);
    g_bfront[kk * 128 + j] = s;
}

__global__ void k_transpose3() {
    int k = blockIdx.y;
    int id = blockIdx.x * 256 + threadIdx.x;
    if (id < 16384) {
        int i = id >> 7, d = id & 127;
        g_wcombT[k * 16384 + d * 128 + i] = g_wcomb[k * 16384 + i * 128 + d];
    }
}

__global__ void k_vecs(const float* __restrict__ bkl) {
    int k = blockIdx.x, i = threadIdx.x;
    float s = 0.f, c = 0.f;
#pragma unroll 4
    for (int d = 0; d < 128; d++) {
        s = fmaf(g_wcomb[k * 16384 + i * 128 + d], bkl[d], s);
        c = fmaf(g_wmkl[k * 16384 + i * 128 + d], g_bfront[k * 128 + d], c);
    }
    g_b2[k * 128 + i] = s;
    g_c3[k * 128 + i] = c;
    if (i == 0) {
        float t = 0.f;
        for (int d = 0; d < 128; d++) t = fmaf(g_bfront[k * 128 + d], bkl[d], t);
        g_sD[k] = t;
    }
}

// ---------------- edge logits + segment max (thread per edge-head) ----------
__global__ void __launch_bounds__(256) k_logits4(
    const int* __restrict__ ei, const int* __restrict__ et,
    const float* __restrict__ rel_pri)
{
    int tid = blockIdx.x * 256 + threadIdx.x;
    if (tid >= EH) return;
    int e = tid >> 2, h = tid & 3;
    int s = ei[e], t = ei[Ee + e], r = et[e];
    const float4* q = (const float4*)(g_qn + (long long)t * 128 + h * 32);
    const float4* kk = (const float4*)(g_knr + ((long long)r * Nn + s) * 128 + h * 32);
    float a0 = 0.f, a1 = 0.f;
#pragma unroll
    for (int i = 0; i < 8; i += 2) {
        float4 x = q[i], y = kk[i];
        a0 += x.x * y.x + x.y * y.y + x.z * y.z + x.w * y.w;
        float4 x1 = q[i + 1], y1 = kk[i + 1];
        a1 += x1.x * y1.x + x1.y * y1.y + x1.z * y1.z + x1.w * y1.w;
    }
    float lg = (a0 + a1) * rel_pri[r * 4 + h] * 0.17677669529663687f;
    g_ex[tid] = lg;
    atomicMaxF(&g_mx[t * 4 + h], lg);
}

// ---------------- exp + denominator (one thread per edge) -------------------
__global__ void k_expden4(const int* __restrict__ ei) {
    int e = blockIdx.x * 256 + threadIdx.x;
    if (e >= Ee) return;
    int t = ei[Ee + e];
    float4 lg = *(const float4*)&g_ex[e * 4];
    float4 m = *(const float4*)&g_mx[t * 4];
    float4 v;
    v.x = expf(lg.x - m.x);
    v.y = expf(lg.y - m.y);
    v.z = expf(lg.z - m.z);
    v.w = expf(lg.w - m.w);
    *(float4*)&g_ex[e * 4] = v;
    atomicAdd(&g_den[t * 4 + 0], v.x);
    atomicAdd(&g_den[t * 4 + 1], v.y);
    atomicAdd(&g_den[t * 4 + 2], v.z);
    atomicAdd(&g_den[t * 4 + 3], v.w);
}

// ---------------- messages (only edge ids < N matter) -----------------------
__global__ void __launch_bounds__(256) k_msg(
    const int* __restrict__ ei, const int* __restrict__ et,
    const float* __restrict__ rel_msg)
{
    extern __shared__ float sh[];
    float* relS = sh;
    float* vnS = sh + RELF;
    for (int i = threadIdx.x; i < RELF; i += 256) relS[i] = rel_msg[i];
    __syncthreads();

    int warp = threadIdx.x >> 5, lane = threadIdx.x & 31;
    float* vW = vnS + warp * 128;
    int stride = gridDim.x * 8;
    for (int n = blockIdx.x * 8 + warp; n < Nn; n += stride) {
        int s = ei[n], t = ei[Ee + n], r = et[n];
        __syncwarp();
#pragma unroll
        for (int h = 0; h < 4; h++)
            vW[h * 32 + lane] = g_vn[(long long)s * 128 + h * 32 + lane];
        __syncwarp();
        float deg = (float)g_deg[n];
#pragma unroll
        for (int h = 0; h < 4; h++) {
            float att = g_ex[n * 4 + h] / (g_den[t * 4 + h] + 1e-16f);
            const float* Am = relS + (r * 4 + h) * 1024;
            float a0 = 0.f, a1 = 0.f;
#pragma unroll
            for (int d = 0; d < 32; d += 2) {
                a0 = fmaf(vW[h * 32 + d],     Am[d * 32 + lane],       a0);
                a1 = fmaf(vW[h * 32 + d + 1], Am[(d + 1) * 32 + lane], a1);
            }
            float vp = a0 + a1;
            float c = att * deg;
            long long o = (long long)n * 128 + h * 32 + lane;
            float m1 = vp * c;
            float m2 = vp * vp * c;
            float m3 = vp * vp * vp * c;
            float s3 = (m3 > 0.f) ? 1.f : ((m3 < 0.f) ? -1.f : 0.f);
            float r3 = s3 * powf(fabsf(m3) + 1e-18f, 0.33333333333333333f);
            g_agg[o] = m1;
            g_agg[ND + o] = m2;
            g_agg[2 * ND + o] = r3;
        }
    }
}

// ---------------- gating + residual + gelu (bilinear form) ------------------
__global__ void __launch_bounds__(256) k_res(const float* __restrict__ meta) {
    int warp = threadIdx.x >> 5, lane = threadIdx.x & 31;
    int n = blockIdx.x * 8 + warp;
    if (n >= Nn) return;
    long long base = (long long)n * 128 + lane * 4;
    const float4 m4 = *(const float4*)&meta[base];
    float r0 = 0.f, r1 = 0.f, r2 = 0.f, r3 = 0.f;
#pragma unroll
    for (int kk = 0; kk < 3; kk++) {
        const float4 u4 = *(const float4*)&g_u[kk * ND + base];
        const float4 a4 = *(const float4*)&g_agg[kk * ND + base];
        const float4 c4 = *(const float4*)&g_c3[kk * 128 + lane * 4];
        float p = m4.x * u4.x + m4.y * u4.y + m4.z * u4.z + m4.w * u4.w
                + a4.x * c4.x + a4.y * c4.y + a4.z * c4.z + a4.w * c4.w;
#pragma unroll
        for (int o = 16; o > 0; o >>= 1) p += __shfl_xor_sync(0xffffffffu, p, o);
        float tt = sigmoidf_(p + g_sD[kk]);
        const float4 am = *(const float4*)&g_aggm[kk * ND + base];
        r0 = fmaf(tt, am.x, r0);
        r1 = fmaf(tt, am.y, r1);
        r2 = fmaf(tt, am.z, r2);
        r3 = fmaf(tt, am.w, r3);
    }
    float4 o;
    o.x = 0.5f * r0 * (1.0f + erff(r0 * 0.70710678118654752f));
    o.y = 0.5f * r1 * (1.0f + erff(r1 * 0.70710678118654752f));
    o.z = 0.5f * r2 * (1.0f + erff(r2 * 0.70710678118654752f));
    o.w = 0.5f * r3 * (1.0f + erff(r3 * 0.70710678118654752f));
    *(float4*)&g_hbuf[base] = o;
}

// ---------------- skip-mix + per-type LayerNorm -----------------------------
__global__ void __launch_bounds__(256) k_final(
    const float* __restrict__ meta, const int* __restrict__ node_type,
    const float* __restrict__ skip, const float* __restrict__ ln_g,
    const float* __restrict__ ln_b, float* __restrict__ out)
{
    int warp = threadIdx.x >> 5, lane = threadIdx.x & 31;
    int n = blockIdx.x * 8 + warp;
    if (n >= Nn) return;
    int t = node_type[n];
    float alpha = sigmoidf_(skip[t]);
    long long base = (long long)n * 128 + lane * 4;
    const float4 tr = *(const float4*)&g_trans[base];
    const float4 x = *(const float4*)&meta[base];
    float y0 = tr.x * alpha + x.x * (1.0f - alpha);
    float y1 = tr.y * alpha + x.y * (1.0f - alpha);
    float y2 = tr.z * alpha + x.z * (1.0f - alpha);
    float y3 = tr.w * alpha + x.w * (1.0f - alpha);
    float s = y0 + y1 + y2 + y3;
    float sq = y0 * y0 + y1 * y1 + y2 * y2 + y3 * y3;
#pragma unroll
    for (int o = 16; o > 0; o >>= 1) {
        s += __shfl_xor_sync(0xffffffffu, s, o);
        sq += __shfl_xor_sync(0xffffffffu, sq, o);
    }
    float mu = s * (1.0f / 128.0f);
    float var = sq * (1.0f / 128.0f) - mu * mu;
    float inv = 1.0f / sqrtf(var + 1e-5f);
    int c = lane * 4;
    const float4 g = *(const float4*)&ln_g[t * 128 + c];
    const float4 b = *(const float4*)&ln_b[t * 128 + c];
    float4 o;
    o.x = (y0 - mu) * inv * g.x + b.x;
    o.y = (y1 - mu) * inv * g.y + b.y;
    o.z = (y2 - mu) * inv * g.z + b.z;
    o.w = (y3 - mu) * inv * g.w + b.w;
    *(float4*)&out[base] = o;
}

// ---------------- host launcher ---------------------------------------------
extern "C" void kernel_launch(void* const* d_in, const int* in_sizes, int n_in,
                              void* d_out, int out_size)
{
    const float* meta      = (const float*)d_in[0];
    const int*   node_type = (const int*)d_in[1];
    const int*   ei        = (const int*)d_in[2];
    const int*   etype     = (const int*)d_in[3];
    const float* q_w = (const float*)d_in[5];
    const float* q_b = (const float*)d_in[6];
    const float* k_w = (const float*)d_in[7];
    const float* k_b = (const float*)d_in[8];
    const float* v_w = (const float*)d_in[9];
    const float* v_b = (const float*)d_in[10];
    const float* a_w = (const float*)d_in[11];
    const float* a_b = (const float*)d_in[12];
    const float* rel_pri = (const float*)d_in[13];
    const float* rel_att = (const float*)d_in[14];
    const float* rel_msg = (const float*)d_in[15];
    const float* WMk = (const float*)d_in[16];
    const float* Wak = (const float*)d_in[17];
    const float* Wq  = (const float*)d_in[18];
    const float* bq  = (const float*)d_in[19];
    const float* Wkl = (const float*)d_in[20];
    const float* bkl = (const float*)d_in[21];
    const float* skip = (const float*)d_in[22];
    const float* ln_g = (const float*)d_in[23];
    const float* ln_b = (const float*)d_in[24];
    float* out = (float*)d_out;

    float *p_qn, *p_kn, *p_vn, *p_knr, *p_agg, *p_aggm, *p_u, *p_hbuf, *p_trans,
          *p_wcomb, *p_wcombT, *p_wmkl, *p_GT, *p_bfront, *p_b2;
    cudaGetSymbolAddress((void**)&p_qn, g_qn);
    cudaGetSymbolAddress((void**)&p_kn, g_kn);
    cudaGetSymbolAddress((void**)&p_vn, g_vn);
    cudaGetSymbolAddress((void**)&p_knr, g_knr);
    cudaGetSymbolAddress((void**)&p_agg, g_agg);
    cudaGetSymbolAddress((void**)&p_aggm, g_aggm);
    cudaGetSymbolAddress((void**)&p_u, g_u);
    cudaGetSymbolAddress((void**)&p_hbuf, g_hbuf);
    cudaGetSymbolAddress((void**)&p_trans, g_trans);
    cudaGetSymbolAddress((void**)&p_wcomb, g_wcomb);
    cudaGetSymbolAddress((void**)&p_wcombT, g_wcombT);
    cudaGetSymbolAddress((void**)&p_wmkl, g_wmkl);
    cudaGetSymbolAddress((void**)&p_GT, g_GT);
    cudaGetSymbolAddress((void**)&p_bfront, g_bfront);
    cudaGetSymbolAddress((void**)&p_b2, g_b2);

    const int SMEM_EDGE = (RELF + 8 * 128) * 4;               // 86016 B
    cudaFuncSetAttribute(k_msg, cudaFuncAttributeMaxDynamicSharedMemorySize, SMEM_EDGE);
    cudaFuncSetAttribute(k_mma_multi, cudaFuncAttributeMaxDynamicSharedMemorySize, MM_TOT);
    cudaFuncSetAttribute(k_mma_rel4, cudaFuncAttributeMaxDynamicSharedMemorySize, R4_TOT);

    dim3 blk(256);
    const int GB = 313;   // ceil(40000/128)

    k_init<<<625, blk>>>();
    k_count<<<1250, blk>>>(node_type, ei);
    k_scan<<<1, 32>>>();
    k_scatter<<<157, blk>>>(node_type);

    // tiny weight products
    k_gemm2<<<dim3(1, 1, 3), blk>>>(Wq, 0, Wak, 16384, nullptr, 0, p_wcomb, 16384, 128);
    k_gemm2<<<dim3(1, 1, 3), blk>>>(WMk, 16384, Wkl, 0, nullptr, 0, p_wmkl, 16384, 128);
    k_bfront<<<3, 128>>>(Wak, bq);
    k_transpose3<<<dim3(64, 3), blk>>>();
    k_gemm2<<<dim3(1, 1, 3), blk>>>(p_wmkl, 16384, p_wcombT, 16384, nullptr, 0, p_GT, 16384, 128);
    k_vecs<<<3, 128>>>(bkl);

    // merged q/k/v typed projections: 9 jobs
    {
        Jobs9 J;
        const float* Ws[3] = {q_w, k_w, v_w};
        const float* Bs_[3] = {q_b, k_b, v_b};
        float* Cs_[3] = {p_qn, p_kn, p_vn};
        for (int m = 0; m < 3; m++)
            for (int t = 0; t < 3; t++)
                J.j[m * 3 + t] = Job{meta, Ws[m] + (long long)t * 16384,
                                     Bs_[m] + (long long)t * 128, Cs_[m], 1, t};
        k_mma_multi<<<dim3(GB, 9), blk, MM_TOT>>>(J);
    }

    // knr per-head: [40000,32] @ [32,160] x 4 heads
    k_mma_rel4<<<dim3(GB, 4), blk, R4_TOT>>>(p_kn, rel_att, p_knr);

    // logits + segment max; exp + denominators
    k_logits4<<<5000, blk>>>(ei, etype, rel_pri);
    k_expden4<<<1250, blk>>>(ei);

    // messages for edge ids < N
    k_msg<<<296, blk, SMEM_EDGE>>>(ei, etype, rel_msg);

    // merged aggm / u: 6 dense jobs
    {
        Jobs9 J;
        for (int kk = 0; kk < 3; kk++) {
            J.j[kk]     = Job{p_agg + (long long)kk * ND, WMk + (long long)kk * 16384,
                              nullptr, p_aggm + (long long)kk * ND, 0, 0};
            J.j[3 + kk] = Job{p_agg + (long long)kk * ND, p_GT + (long long)kk * 16384,
                              p_b2 + (long long)kk * 128, p_u + (long long)kk * ND, 0, 0};
        }
        for (int z = 6; z < 9; z++) J.j[z] = J.j[0];
        k_mma_multi<<<dim3(GB, 6), blk, MM_TOT>>>(J);
    }

    k_res<<<5000, blk>>>(meta);

    // trans = typed(gelu(res), a_w, a_b): 3 typed jobs
    {
        Jobs9 J;
        for (int t = 0; t < 3; t++)
            J.j[t] = Job{p_hbuf, a_w + (long long)t * 16384,
                         a_b + (long long)t * 128, p_trans, 1, t};
        for (int z = 3; z < 9; z++) J.j[z] = J.j[0];
        k_mma_multi<<<dim3(GB, 3), blk, MM_TOT>>>(J);
    }

    k_final<<<5000, blk>>>(meta, node_type, skip, ln_g, ln_b, out);
}